// round 3
// baseline (speedup 1.0000x reference)
#include <cuda_runtime.h>
#include <math.h>

#define B_   2
#define S_   2048
#define H_   1024
#define NH_  16
#define HD_  64
#define BSH  (B_*S_*H_)

__device__ float g_Qt[B_*NH_*HD_*S_];   // [b][h][d][s], scaled by 1/8
__device__ float g_Kt[B_*NH_*HD_*S_];   // [b][h][d][s]
__device__ float g_V [B_*NH_*S_*HD_];   // [b][h][s][d]
__device__ float g_gq[B_*H_];
__device__ float g_u [B_*H_*NH_];       // [b][k][h]
__device__ float g_c [B_*NH_];
__device__ double g_red[3][32];         // 0=entropy 1=influence 2=concentration

__global__ void init_kernel() {
    int t = threadIdx.x;
    if (t < 96) ((double*)g_red)[t] = 0.0;
}

// ---- QKV projections: z=0 Q (scaled, d-major), z=1 K (d-major), z=2 V ------
__global__ void __launch_bounds__(256) proj_kernel(
    const float* __restrict__ hs,
    const float* __restrict__ Wq, const float* __restrict__ bq,
    const float* __restrict__ Wk, const float* __restrict__ bk,
    const float* __restrict__ Wv, const float* __restrict__ bv)
{
    __shared__ float sA[16][132];
    __shared__ float sB[16][132];
    int mode = blockIdx.z;
    const float* W  = mode==0 ? Wq : (mode==1 ? Wk : Wv);
    const float* bb = mode==0 ? bq : (mode==1 ? bk : bv);
    int m0 = blockIdx.y * 128, n0 = blockIdx.x * 128;
    int tid = threadIdx.x, warp = tid >> 5, lane = tid & 31;
    int lr = lane >> 4, lc = lane & 15;
    int rowBase = warp*16 + lr*4;
    int colBase = lc*4;

    float acc[8][8];
    #pragma unroll
    for (int i=0;i<8;i++)
        #pragma unroll
        for (int j=0;j<8;j++) acc[i][j] = 0.f;

    for (int k0 = 0; k0 < H_; k0 += 16) {
        #pragma unroll
        for (int i=0;i<2;i++){
            int g = tid + i*256;
            int m = g >> 2, kv = (g & 3) << 2;
            float4 v = *(const float4*)(hs + (size_t)(m0+m)*H_ + k0 + kv);
            sA[kv+0][m]=v.x; sA[kv+1][m]=v.y; sA[kv+2][m]=v.z; sA[kv+3][m]=v.w;
        }
        #pragma unroll
        for (int i=0;i<2;i++){
            int g = tid + i*256;
            int k = g >> 5, nv = (g & 31) << 2;
            *(float4*)&sB[k][nv] = *(const float4*)(W + (size_t)(k0+k)*H_ + n0 + nv);
        }
        __syncthreads();
        #pragma unroll
        for (int kk=0;kk<16;kk++){
            float a[8], bf[8];
            *(float4*)&a[0]  = *(float4*)&sA[kk][rowBase];
            *(float4*)&a[4]  = *(float4*)&sA[kk][rowBase+8];
            *(float4*)&bf[0] = *(float4*)&sB[kk][colBase];
            *(float4*)&bf[4] = *(float4*)&sB[kk][colBase+64];
            #pragma unroll
            for (int i=0;i<8;i++)
                #pragma unroll
                for (int j=0;j<8;j++)
                    acc[i][j] += a[i]*bf[j];
        }
        __syncthreads();
    }

    if (mode < 2) {
        float scale = (mode==0) ? 0.125f : 1.0f;
        float* dst = (mode==0) ? g_Qt : g_Kt;
        #pragma unroll
        for (int j=0;j<8;j++){
            int n = n0 + colBase + j + ((j>=4)?60:0);
            float bv_ = bb[n];
            int h = n >> 6, d = n & 63;
            #pragma unroll
            for (int g2=0; g2<2; g2++){
                int m = m0 + rowBase + g2*8;
                int b = m >> 11, s = m & 2047;
                float4 v;
                v.x = (acc[g2*4+0][j] + bv_) * scale;
                v.y = (acc[g2*4+1][j] + bv_) * scale;
                v.z = (acc[g2*4+2][j] + bv_) * scale;
                v.w = (acc[g2*4+3][j] + bv_) * scale;
                *(float4*)(dst + (((size_t)(b*NH_+h)*HD_ + d) << 11) + s) = v;
            }
        }
    } else {
        #pragma unroll
        for (int i=0;i<8;i++){
            int m = m0 + rowBase + i + ((i>=4)?4:0);
            int b = m >> 11, s = m & 2047;
            #pragma unroll
            for (int g2=0; g2<2; g2++){
                int n = n0 + colBase + g2*64;
                int h = n >> 6, d = n & 63;
                float4 v;
                v.x = acc[i][g2*4+0] + bb[n+0];
                v.y = acc[i][g2*4+1] + bb[n+1];
                v.z = acc[i][g2*4+2] + bb[n+2];
                v.w = acc[i][g2*4+3] + bb[n+3];
                *(float4*)(g_V + (((size_t)(b*NH_+h)*S_ + s) << 6) + d) = v;
            }
        }
    }
}

__global__ void gq_kernel(const float* __restrict__ gov,
                          const float* __restrict__ Wgq,
                          const float* __restrict__ bgq)
{
    __shared__ float sg[H_];
    int b = blockIdx.y;
    int n = blockIdx.x*256 + threadIdx.x;
    for (int i=threadIdx.x; i<H_/4; i+=256)
        *(float4*)&sg[i*4] = *(const float4*)(gov + b*H_ + i*4);
    __syncthreads();
    float acc = 0.f;
    for (int k=0;k<H_;k++)
        acc += sg[k] * Wgq[(size_t)k*H_ + n];
    g_gq[b*H_ + n] = acc + bgq[n];
}

__global__ void u_kernel(const float* __restrict__ Wgk)
{
    int idx = blockIdx.x*256 + threadIdx.x;   // b*16384 + k*16 + h
    int h = idx & 15;
    int k = (idx >> 4) & 1023;
    int b = idx >> 14;
    const float* wrow = Wgk + (size_t)k*H_ + h*HD_;
    const float* gq   = g_gq + b*H_ + h*HD_;
    float acc = 0.f;
    #pragma unroll
    for (int d=0; d<HD_; d+=4){
        float4 w = *(const float4*)(wrow + d);
        float4 g = *(const float4*)(gq + d);
        acc += w.x*g.x + w.y*g.y + w.z*g.z + w.w*g.w;
    }
    g_u[idx] = acc;
}

__global__ void c_kernel(const float* __restrict__ bgk)
{
    int t = threadIdx.x;
    if (t < 32){
        int b = t >> 4, h = t & 15;
        const float* gq = g_gq + b*H_ + h*HD_;
        const float* bp = bgk + h*HD_;
        float acc = 0.f;
        #pragma unroll
        for (int d=0;d<HD_;d++) acc += bp[d]*gq[d];
        g_c[t] = acc;
    }
}

__global__ void gov_kernel(const float* __restrict__ hs)
{
    __shared__ float shs[H_];
    __shared__ float sred[4][16];
    int bs_ = blockIdx.x;
    int b = bs_ >> 11;
    int tid = threadIdx.x;   // 128
    const float* row = hs + (size_t)bs_ * H_;
    for (int i=tid; i<H_/4; i+=128)
        *(float4*)&shs[i*4] = *(const float4*)(row + i*4);
    __syncthreads();
    float acc[16];
    #pragma unroll
    for (int h=0;h<16;h++) acc[h]=0.f;
    const float* ub = g_u + b*16384;
    #pragma unroll
    for (int kk=0;kk<8;kk++){
        int k = kk*128 + tid;
        float hv = shs[k];
        const float* up = ub + k*16;
        #pragma unroll
        for (int h4=0; h4<4; h4++){
            float4 u4 = *(const float4*)(up + h4*4);
            acc[h4*4+0] += hv*u4.x;
            acc[h4*4+1] += hv*u4.y;
            acc[h4*4+2] += hv*u4.z;
            acc[h4*4+3] += hv*u4.w;
        }
    }
    #pragma unroll
    for (int h=0;h<16;h++){
        #pragma unroll
        for (int off=16; off>0; off>>=1)
            acc[h] += __shfl_xor_sync(0xffffffffu, acc[h], off);
    }
    int warp = tid>>5, lane = tid&31;
    if (lane==0){
        #pragma unroll
        for (int h=0;h<16;h++) sred[warp][h] = acc[h];
    }
    __syncthreads();
    if (tid < 16){
        float g = sred[0][tid]+sred[1][tid]+sred[2][tid]+sred[3][tid] + g_c[b*16+tid];
        float v = fabsf(g);
        #pragma unroll
        for (int off=8; off>0; off>>=1)
            v += __shfl_xor_sync(0xffffu, v, off);
        if (tid==0) atomicAdd(&g_red[1][bs_ & 31], (double)v);
    }
}

#define FLASH_SMEM ((2*64*132 + 128*68 + 128*132)*4)

__global__ void __launch_bounds__(256,1) flash_kernel(float* __restrict__ out)
{
    extern __shared__ float sm[];
    float* sQT = sm;                    // [64][132]
    float* sKT = sm + 64*132;           // [64][132]
    float* sV  = sm + 2*64*132;         // [128][68]
    float* sPT = sV + 128*68;           // [128][132]

    int q0 = blockIdx.x * 128;
    int h  = blockIdx.y;
    int b  = blockIdx.z;
    const float* Qbh = g_Qt + (size_t)(b*NH_+h)*HD_*S_;
    const float* Kbh = g_Kt + (size_t)(b*NH_+h)*HD_*S_;
    const float* Vbh = g_V  + (size_t)(b*NH_+h)*S_*HD_;

    int tid = threadIdx.x, warp = tid >> 5, lane = tid & 31;
    int lr = lane >> 4, lc = lane & 15;
    int rowBase = warp*16 + lr*4;
    int colV = lc*4;

    for (int g = tid; g < 64*32; g += 256){
        int d = g >> 5, c = (g & 31) << 2;
        *(float4*)&sQT[d*132 + c] = *(const float4*)(Qbh + (size_t)d*S_ + q0 + c);
    }

    float oacc[8][4], mrow[8], lrow[8], trow[8];
    #pragma unroll
    for (int i=0;i<8;i++){
        mrow[i] = -1e30f; lrow[i] = 0.f; trow[i] = 0.f;
        #pragma unroll
        for (int c=0;c<4;c++) oacc[i][c] = 0.f;
    }

    for (int j0 = 0; j0 < S_; j0 += 128){
        __syncthreads();
        for (int g = tid; g < 64*32; g += 256){
            int d = g >> 5, c = (g & 31) << 2;
            *(float4*)&sKT[d*132 + c] = *(const float4*)(Kbh + (size_t)d*S_ + j0 + c);
        }
        for (int g = tid; g < 128*16; g += 256){
            int j = g >> 4, dv = (g & 15) << 2;
            *(float4*)&sV[j*68 + dv] = *(const float4*)(Vbh + (size_t)(j0+j)*HD_ + dv);
        }
        __syncthreads();

        float sc_[8][8];
        #pragma unroll
        for (int i=0;i<8;i++)
            #pragma unroll
            for (int j=0;j<8;j++) sc_[i][j] = 0.f;
        #pragma unroll 8
        for (int d=0; d<64; d++){
            float a[8], kf[8];
            *(float4*)&a[0]  = *(float4*)&sQT[d*132 + rowBase];
            *(float4*)&a[4]  = *(float4*)&sQT[d*132 + rowBase + 8];
            *(float4*)&kf[0] = *(float4*)&sKT[d*132 + lc*4];
            *(float4*)&kf[4] = *(float4*)&sKT[d*132 + lc*4 + 64];
            #pragma unroll
            for (int i=0;i<8;i++)
                #pragma unroll
                for (int j=0;j<8;j++)
                    sc_[i][j] += a[i]*kf[j];
        }

        #pragma unroll
        for (int i=0;i<8;i++){
            float tm = sc_[i][0];
            #pragma unroll
            for (int j=1;j<8;j++) tm = fmaxf(tm, sc_[i][j]);
            #pragma unroll
            for (int off=8; off>0; off>>=1)
                tm = fmaxf(tm, __shfl_xor_sync(0xffffffffu, tm, off));
            float mn = fmaxf(mrow[i], tm);
            float la = 0.f, ta = 0.f;
            #pragma unroll
            for (int j=0;j<8;j++){
                float s = sc_[i][j];
                float e = __expf(s - mn);
                sc_[i][j] = e;
                la += e;
                ta += e*s;
            }
            #pragma unroll
            for (int off=8; off>0; off>>=1){
                la += __shfl_xor_sync(0xffffffffu, la, off);
                ta += __shfl_xor_sync(0xffffffffu, ta, off);
            }
            float scl = __expf(mrow[i]-mn);
            lrow[i] = lrow[i]*scl + la;
            trow[i] = trow[i]*scl + ta;
            mrow[i] = mn;
            #pragma unroll
            for (int c=0;c<4;c++) oacc[i][c] *= scl;
        }

        #pragma unroll
        for (int j=0;j<8;j++){
            int cc = lc*4 + j + ((j>=4)?60:0);
            float4 v0 = make_float4(sc_[0][j],sc_[1][j],sc_[2][j],sc_[3][j]);
            float4 v1 = make_float4(sc_[4][j],sc_[5][j],sc_[6][j],sc_[7][j]);
            *(float4*)&sPT[cc*132 + rowBase]     = v0;
            *(float4*)&sPT[cc*132 + rowBase + 8] = v1;
        }
        __syncthreads();

        #pragma unroll 4
        for (int j=0;j<128;j++){
            float pf[8], vf[4];
            *(float4*)&pf[0] = *(float4*)&sPT[j*132 + rowBase];
            *(float4*)&pf[4] = *(float4*)&sPT[j*132 + rowBase + 8];
            *(float4*)&vf[0] = *(float4*)&sV[j*68 + colV];
            #pragma unroll
            for (int i=0;i<8;i++)
                #pragma unroll
                for (int c=0;c<4;c++)
                    oacc[i][c] += pf[i]*vf[c];
        }
    }

    // epilogue: O/l, entropy = m + log l - t/l - S*eps, concentration = 1/l
    #pragma unroll
    for (int i=0;i<8;i++){
        int r = rowBase + i + ((i>=4)?4:0);
        float inv = 1.0f / lrow[i];
        float4 v = make_float4(oacc[i][0]*inv, oacc[i][1]*inv,
                               oacc[i][2]*inv, oacc[i][3]*inv);
        *(float4*)(out + ((size_t)b*S_ + (q0+r))*H_ + h*HD_ + colV) = v;
    }
    if (lc == 0){
        double es = 0.0, cs = 0.0;
        #pragma unroll
        for (int i=0;i<8;i++){
            es += (double)(mrow[i] + logf(lrow[i]) - trow[i]/lrow[i] - 2.048e-5f);
            cs += (double)(1.0f / lrow[i]);
        }
        atomicAdd(&g_red[0][tid & 31], es);
        atomicAdd(&g_red[2][tid & 31], cs);
    }
}

__global__ void fin_kernel(float* __restrict__ out, int out_size)
{
    int t = threadIdx.x;  // 32
    double e = g_red[0][t], f = g_red[1][t], c = g_red[2][t];
    #pragma unroll
    for (int off=16; off>0; off>>=1){
        e += __shfl_xor_sync(0xffffffffu, e, off);
        f += __shfl_xor_sync(0xffffffffu, f, off);
        c += __shfl_xor_sync(0xffffffffu, c, off);
    }
    if (t == 0 && out_size >= BSH + 3){
        out[BSH+0] = (float)(e / 65536.0);
        out[BSH+1] = (float)(f / 65536.0);
        out[BSH+2] = (float)(c / 65536.0);
    }
}

extern "C" void kernel_launch(void* const* d_in, const int* in_sizes, int n_in,
                              void* d_out, int out_size) {
    const float* hs   = (const float*)d_in[0];
    const float* gov  = (const float*)d_in[1];
    const float* Wq   = (const float*)d_in[2];
    const float* bq   = (const float*)d_in[3];
    const float* Wk   = (const float*)d_in[4];
    const float* bk   = (const float*)d_in[5];
    const float* Wv   = (const float*)d_in[6];
    const float* bv   = (const float*)d_in[7];
    const float* Wgq  = (const float*)d_in[8];
    const float* bgq  = (const float*)d_in[9];
    const float* Wgk  = (const float*)d_in[10];
    const float* bgk  = (const float*)d_in[11];
    float* out = (float*)d_out;

    init_kernel<<<1, 96>>>();
    proj_kernel<<<dim3(H_/128, B_*S_/128, 3), 256>>>(hs, Wq, bq, Wk, bk, Wv, bv);
    gq_kernel<<<dim3(H_/256, B_), 256>>>(gov, Wgq, bgq);
    u_kernel<<<(B_*H_*NH_)/256, 256>>>(Wgk);
    c_kernel<<<1, 32>>>(bgk);
    gov_kernel<<<B_*S_, 128>>>(hs);
    cudaFuncSetAttribute(flash_kernel, cudaFuncAttributeMaxDynamicSharedMemorySize, FLASH_SMEM);
    flash_kernel<<<dim3(S_/128, NH_, B_), 256, FLASH_SMEM>>>(out);
    fin_kernel<<<1, 32>>>(out, out_size);
}

// round 4
// speedup vs baseline: 1.0721x; 1.0721x over previous
#include <cuda_runtime.h>
#include <math.h>

#define B_   2
#define S_   2048
#define H_   1024
#define NH_  16
#define HD_  64
#define BSH  (B_*S_*H_)

typedef unsigned long long u64;

__device__ __forceinline__ u64 bcast2(float x){
    u64 r; asm("mov.b64 %0, {%1, %1};" : "=l"(r) : "f"(x)); return r;
}
__device__ __forceinline__ u64 pack2(float x, float y){
    u64 r; asm("mov.b64 %0, {%1, %2};" : "=l"(r) : "f"(x), "f"(y)); return r;
}
__device__ __forceinline__ float2 unpk(u64 a){
    float2 v; asm("mov.b64 {%0, %1}, %2;" : "=f"(v.x), "=f"(v.y) : "l"(a)); return v;
}
__device__ __forceinline__ u64 ffma2(u64 a, u64 b, u64 c){
    u64 d; asm("fma.rn.f32x2 %0, %1, %2, %3;" : "=l"(d) : "l"(a), "l"(b), "l"(c)); return d;
}
__device__ __forceinline__ u64 fmul2(u64 a, u64 b){
    u64 d; asm("mul.rn.f32x2 %0, %1, %2;" : "=l"(d) : "l"(a), "l"(b)); return d;
}

__device__ float g_Qt[B_*NH_*HD_*S_];   // [b][h][d][s], scaled by 1/8
__device__ float g_Kt[B_*NH_*HD_*S_];   // [b][h][d][s]
__device__ float g_V [B_*NH_*S_*HD_];   // [b][h][s][d]
__device__ float g_gq[B_*H_];
__device__ float g_u [B_*H_*NH_];       // [b][k][h]
__device__ float g_c [B_*NH_];
__device__ double g_red[3][32];         // 0=entropy 1=influence 2=concentration

__global__ void init_kernel() {
    int t = threadIdx.x;
    if (t < 96) ((double*)g_red)[t] = 0.0;
}

// ---- QKV projections: z=0 Q (scaled, d-major), z=1 K (d-major), z=2 V ------
__global__ void __launch_bounds__(256) proj_kernel(
    const float* __restrict__ hs,
    const float* __restrict__ Wq, const float* __restrict__ bq,
    const float* __restrict__ Wk, const float* __restrict__ bk,
    const float* __restrict__ Wv, const float* __restrict__ bv)
{
    __shared__ float sA[16][132];
    __shared__ float sB[16][132];
    int mode = blockIdx.z;
    const float* W  = mode==0 ? Wq : (mode==1 ? Wk : Wv);
    const float* bb = mode==0 ? bq : (mode==1 ? bk : bv);
    int m0 = blockIdx.y * 128, n0 = blockIdx.x * 128;
    int tid = threadIdx.x, warp = tid >> 5, lane = tid & 31;
    int lr = lane >> 4, lc = lane & 15;
    int rowBase = warp*16 + lr*4;
    int colBase = lc*4;

    u64 acc2[4][8];   // row-pairs (logical rows 0..7) x 8 cols
    #pragma unroll
    for (int i=0;i<4;i++)
        #pragma unroll
        for (int j=0;j<8;j++) acc2[i][j] = 0ull;

    for (int k0 = 0; k0 < H_; k0 += 16) {
        #pragma unroll
        for (int i=0;i<2;i++){
            int g = tid + i*256;
            int m = g >> 2, kv = (g & 3) << 2;
            float4 v = *(const float4*)(hs + (size_t)(m0+m)*H_ + k0 + kv);
            sA[kv+0][m]=v.x; sA[kv+1][m]=v.y; sA[kv+2][m]=v.z; sA[kv+3][m]=v.w;
        }
        #pragma unroll
        for (int i=0;i<2;i++){
            int g = tid + i*256;
            int k = g >> 5, nv = (g & 31) << 2;
            *(float4*)&sB[k][nv] = *(const float4*)(W + (size_t)(k0+k)*H_ + n0 + nv);
        }
        __syncthreads();
        #pragma unroll 4
        for (int kk=0;kk<16;kk++){
            ulonglong2 A0 = *(ulonglong2*)&sA[kk][rowBase];
            ulonglong2 A1 = *(ulonglong2*)&sA[kk][rowBase+8];
            u64 a2[4] = {A0.x, A0.y, A1.x, A1.y};
            float4 bf0 = *(float4*)&sB[kk][colBase];
            float4 bf1 = *(float4*)&sB[kk][colBase+64];
            u64 b2[8];
            b2[0]=bcast2(bf0.x); b2[1]=bcast2(bf0.y); b2[2]=bcast2(bf0.z); b2[3]=bcast2(bf0.w);
            b2[4]=bcast2(bf1.x); b2[5]=bcast2(bf1.y); b2[6]=bcast2(bf1.z); b2[7]=bcast2(bf1.w);
            #pragma unroll
            for (int i=0;i<4;i++)
                #pragma unroll
                for (int j=0;j<8;j++)
                    acc2[i][j] = ffma2(a2[i], b2[j], acc2[i][j]);
        }
        __syncthreads();
    }

    // unpack to logical acc[i][j], i: rows rowBase+{0..3}, rowBase+8+{0..3}
    float acc[8][8];
    #pragma unroll
    for (int i2=0;i2<4;i2++)
        #pragma unroll
        for (int j=0;j<8;j++){
            float2 v = unpk(acc2[i2][j]);
            acc[2*i2][j] = v.x; acc[2*i2+1][j] = v.y;
        }

    if (mode < 2) {
        float scale = (mode==0) ? 0.125f : 1.0f;
        float* dst = (mode==0) ? g_Qt : g_Kt;
        #pragma unroll
        for (int j=0;j<8;j++){
            int n = n0 + colBase + j + ((j>=4)?60:0);
            float bv_ = bb[n];
            int h = n >> 6, d = n & 63;
            #pragma unroll
            for (int g2=0; g2<2; g2++){
                int m = m0 + rowBase + g2*8;
                int b = m >> 11, s = m & 2047;
                float4 v;
                v.x = (acc[g2*4+0][j] + bv_) * scale;
                v.y = (acc[g2*4+1][j] + bv_) * scale;
                v.z = (acc[g2*4+2][j] + bv_) * scale;
                v.w = (acc[g2*4+3][j] + bv_) * scale;
                *(float4*)(dst + (((size_t)(b*NH_+h)*HD_ + d) << 11) + s) = v;
            }
        }
    } else {
        #pragma unroll
        for (int i=0;i<8;i++){
            int m = m0 + rowBase + i + ((i>=4)?4:0);
            int b = m >> 11, s = m & 2047;
            #pragma unroll
            for (int g2=0; g2<2; g2++){
                int n = n0 + colBase + g2*64;
                int h = n >> 6, d = n & 63;
                float4 v;
                v.x = acc[i][g2*4+0] + bb[n+0];
                v.y = acc[i][g2*4+1] + bb[n+1];
                v.z = acc[i][g2*4+2] + bb[n+2];
                v.w = acc[i][g2*4+3] + bb[n+3];
                *(float4*)(g_V + (((size_t)(b*NH_+h)*S_ + s) << 6) + d) = v;
            }
        }
    }
}

__global__ void gq_kernel(const float* __restrict__ gov,
                          const float* __restrict__ Wgq,
                          const float* __restrict__ bgq)
{
    __shared__ float sg[H_];
    int b = blockIdx.y;
    int n = blockIdx.x*256 + threadIdx.x;
    for (int i=threadIdx.x; i<H_/4; i+=256)
        *(float4*)&sg[i*4] = *(const float4*)(gov + b*H_ + i*4);
    __syncthreads();
    float acc = 0.f;
    for (int k=0;k<H_;k++)
        acc += sg[k] * Wgq[(size_t)k*H_ + n];
    g_gq[b*H_ + n] = acc + bgq[n];
}

__global__ void u_kernel(const float* __restrict__ Wgk)
{
    int idx = blockIdx.x*256 + threadIdx.x;   // b*16384 + k*16 + h
    int h = idx & 15;
    int k = (idx >> 4) & 1023;
    int b = idx >> 14;
    const float* wrow = Wgk + (size_t)k*H_ + h*HD_;
    const float* gq   = g_gq + b*H_ + h*HD_;
    float acc = 0.f;
    #pragma unroll
    for (int d=0; d<HD_; d+=4){
        float4 w = *(const float4*)(wrow + d);
        float4 g = *(const float4*)(gq + d);
        acc += w.x*g.x + w.y*g.y + w.z*g.z + w.w*g.w;
    }
    g_u[idx] = acc;
}

__global__ void c_kernel(const float* __restrict__ bgk)
{
    int t = threadIdx.x;
    if (t < 32){
        int b = t >> 4, h = t & 15;
        const float* gq = g_gq + b*H_ + h*HD_;
        const float* bp = bgk + h*HD_;
        float acc = 0.f;
        #pragma unroll
        for (int d=0;d<HD_;d++) acc += bp[d]*gq[d];
        g_c[t] = acc;
    }
}

__global__ void gov_kernel(const float* __restrict__ hs)
{
    __shared__ float shs[H_];
    __shared__ float sred[4][16];
    int bs_ = blockIdx.x;
    int b = bs_ >> 11;
    int tid = threadIdx.x;   // 128
    const float* row = hs + (size_t)bs_ * H_;
    for (int i=tid; i<H_/4; i+=128)
        *(float4*)&shs[i*4] = *(const float4*)(row + i*4);
    __syncthreads();
    float acc[16];
    #pragma unroll
    for (int h=0;h<16;h++) acc[h]=0.f;
    const float* ub = g_u + b*16384;
    #pragma unroll
    for (int kk=0;kk<8;kk++){
        int k = kk*128 + tid;
        float hv = shs[k];
        const float* up = ub + k*16;
        #pragma unroll
        for (int h4=0; h4<4; h4++){
            float4 u4 = *(const float4*)(up + h4*4);
            acc[h4*4+0] += hv*u4.x;
            acc[h4*4+1] += hv*u4.y;
            acc[h4*4+2] += hv*u4.z;
            acc[h4*4+3] += hv*u4.w;
        }
    }
    #pragma unroll
    for (int h=0;h<16;h++){
        #pragma unroll
        for (int off=16; off>0; off>>=1)
            acc[h] += __shfl_xor_sync(0xffffffffu, acc[h], off);
    }
    int warp = tid>>5, lane = tid&31;
    if (lane==0){
        #pragma unroll
        for (int h=0;h<16;h++) sred[warp][h] = acc[h];
    }
    __syncthreads();
    if (tid < 16){
        float g = sred[0][tid]+sred[1][tid]+sred[2][tid]+sred[3][tid] + g_c[b*16+tid];
        float v = fabsf(g);
        #pragma unroll
        for (int off=8; off>0; off>>=1)
            v += __shfl_xor_sync(0xffffu, v, off);
        if (tid==0) atomicAdd(&g_red[1][bs_ & 31], (double)v);
    }
}

#define FLASH_SMEM ((2*64*132 + 128*68 + 128*132)*4)

__global__ void __launch_bounds__(256,1) flash_kernel(float* __restrict__ out)
{
    extern __shared__ float sm[];
    float* sQT = sm;                    // [64][132]
    float* sKT = sm + 64*132;           // [64][132]
    float* sV  = sm + 2*64*132;         // [128][68]
    float* sPT = sV + 128*68;           // [128][132]

    int q0 = blockIdx.x * 128;
    int h  = blockIdx.y;
    int b  = blockIdx.z;
    const float* Qbh = g_Qt + (size_t)(b*NH_+h)*HD_*S_;
    const float* Kbh = g_Kt + (size_t)(b*NH_+h)*HD_*S_;
    const float* Vbh = g_V  + (size_t)(b*NH_+h)*S_*HD_;

    int tid = threadIdx.x, warp = tid >> 5, lane = tid & 31;
    int lr = lane >> 4, lc = lane & 15;
    int rowBase = warp*16 + lr*4;
    int colV = lc*4;

    for (int g = tid; g < 64*32; g += 256){
        int d = g >> 5, c = (g & 31) << 2;
        *(float4*)&sQT[d*132 + c] = *(const float4*)(Qbh + (size_t)d*S_ + q0 + c);
    }

    u64 oacc2[4][4];                    // row-pairs x 4 O-cols
    float mrow[8], lrow[8], trow[8];
    #pragma unroll
    for (int i=0;i<8;i++){ mrow[i] = -1e30f; lrow[i] = 0.f; trow[i] = 0.f; }
    #pragma unroll
    for (int i=0;i<4;i++)
        #pragma unroll
        for (int c=0;c<4;c++) oacc2[i][c] = 0ull;

    for (int j0 = 0; j0 < S_; j0 += 128){
        __syncthreads();
        for (int g = tid; g < 64*32; g += 256){
            int d = g >> 5, c = (g & 31) << 2;
            *(float4*)&sKT[d*132 + c] = *(const float4*)(Kbh + (size_t)d*S_ + j0 + c);
        }
        for (int g = tid; g < 128*16; g += 256){
            int j = g >> 4, dv = (g & 15) << 2;
            *(float4*)&sV[j*68 + dv] = *(const float4*)(Vbh + (size_t)(j0+j)*HD_ + dv);
        }
        __syncthreads();

        // S = Q @ K^T  (scale folded into Q) — packed row-pairs
        u64 sc2[4][8];
        #pragma unroll
        for (int i=0;i<4;i++)
            #pragma unroll
            for (int j=0;j<8;j++) sc2[i][j] = 0ull;
        #pragma unroll 4
        for (int d=0; d<64; d++){
            ulonglong2 A0 = *(ulonglong2*)&sQT[d*132 + rowBase];
            ulonglong2 A1 = *(ulonglong2*)&sQT[d*132 + rowBase + 8];
            u64 a2[4] = {A0.x, A0.y, A1.x, A1.y};
            float4 k0 = *(float4*)&sKT[d*132 + lc*4];
            float4 k1 = *(float4*)&sKT[d*132 + lc*4 + 64];
            u64 b2[8];
            b2[0]=bcast2(k0.x); b2[1]=bcast2(k0.y); b2[2]=bcast2(k0.z); b2[3]=bcast2(k0.w);
            b2[4]=bcast2(k1.x); b2[5]=bcast2(k1.y); b2[6]=bcast2(k1.z); b2[7]=bcast2(k1.w);
            #pragma unroll
            for (int i=0;i<4;i++)
                #pragma unroll
                for (int j=0;j<8;j++)
                    sc2[i][j] = ffma2(a2[i], b2[j], sc2[i][j]);
        }

        float sc_[8][8];
        #pragma unroll
        for (int i2=0;i2<4;i2++)
            #pragma unroll
            for (int j=0;j<8;j++){
                float2 v = unpk(sc2[i2][j]);
                sc_[2*i2][j] = v.x; sc_[2*i2+1][j] = v.y;
            }

        float scl8[8];
        #pragma unroll
        for (int i=0;i<8;i++){
            float tm = sc_[i][0];
            #pragma unroll
            for (int j=1;j<8;j++) tm = fmaxf(tm, sc_[i][j]);
            #pragma unroll
            for (int off=8; off>0; off>>=1)
                tm = fmaxf(tm, __shfl_xor_sync(0xffffffffu, tm, off));
            float mn = fmaxf(mrow[i], tm);
            float la = 0.f, ta = 0.f;
            #pragma unroll
            for (int j=0;j<8;j++){
                float s = sc_[i][j];
                float e = __expf(s - mn);
                sc_[i][j] = e;
                la += e;
                ta += e*s;
            }
            #pragma unroll
            for (int off=8; off>0; off>>=1){
                la += __shfl_xor_sync(0xffffffffu, la, off);
                ta += __shfl_xor_sync(0xffffffffu, ta, off);
            }
            float scl = __expf(mrow[i]-mn);
            lrow[i] = lrow[i]*scl + la;
            trow[i] = trow[i]*scl + ta;
            mrow[i] = mn;
            scl8[i] = scl;
        }
        #pragma unroll
        for (int i2=0;i2<4;i2++){
            u64 sp = pack2(scl8[2*i2], scl8[2*i2+1]);
            #pragma unroll
            for (int c=0;c<4;c++) oacc2[i2][c] = fmul2(oacc2[i2][c], sp);
        }

        // stage P^T
        #pragma unroll
        for (int j=0;j<8;j++){
            int cc = lc*4 + j + ((j>=4)?60:0);
            float4 v0 = make_float4(sc_[0][j],sc_[1][j],sc_[2][j],sc_[3][j]);
            float4 v1 = make_float4(sc_[4][j],sc_[5][j],sc_[6][j],sc_[7][j]);
            *(float4*)&sPT[cc*132 + rowBase]     = v0;
            *(float4*)&sPT[cc*132 + rowBase + 8] = v1;
        }
        __syncthreads();

        // O += P @ V — packed row-pairs, broadcast V
        #pragma unroll 4
        for (int j=0;j<128;j++){
            ulonglong2 P0 = *(ulonglong2*)&sPT[j*132 + rowBase];
            ulonglong2 P1 = *(ulonglong2*)&sPT[j*132 + rowBase + 8];
            u64 p2[4] = {P0.x, P0.y, P1.x, P1.y};
            float4 vv = *(float4*)&sV[j*68 + colV];
            u64 v2[4] = {bcast2(vv.x), bcast2(vv.y), bcast2(vv.z), bcast2(vv.w)};
            #pragma unroll
            for (int i=0;i<4;i++)
                #pragma unroll
                for (int c=0;c<4;c++)
                    oacc2[i][c] = ffma2(p2[i], v2[c], oacc2[i][c]);
        }
    }

    // unpack O
    float accf[8][4];
    #pragma unroll
    for (int i2=0;i2<4;i2++)
        #pragma unroll
        for (int c=0;c<4;c++){
            float2 v = unpk(oacc2[i2][c]);
            accf[2*i2][c] = v.x; accf[2*i2+1][c] = v.y;
        }

    // epilogue: O/l, entropy = m + log l - t/l - S*eps, concentration = 1/l
    #pragma unroll
    for (int i=0;i<8;i++){
        int r = rowBase + i + ((i>=4)?4:0);
        float inv = 1.0f / lrow[i];
        float4 v = make_float4(accf[i][0]*inv, accf[i][1]*inv,
                               accf[i][2]*inv, accf[i][3]*inv);
        *(float4*)(out + ((size_t)b*S_ + (q0+r))*H_ + h*HD_ + colV) = v;
    }
    if (lc == 0){
        double es = 0.0, cs = 0.0;
        #pragma unroll
        for (int i=0;i<8;i++){
            es += (double)(mrow[i] + logf(lrow[i]) - trow[i]/lrow[i] - 2.048e-5f);
            cs += (double)(1.0f / lrow[i]);
        }
        atomicAdd(&g_red[0][tid & 31], es);
        atomicAdd(&g_red[2][tid & 31], cs);
    }
}

__global__ void fin_kernel(float* __restrict__ out, int out_size)
{
    int t = threadIdx.x;  // 32
    double e = g_red[0][t], f = g_red[1][t], c = g_red[2][t];
    #pragma unroll
    for (int off=16; off>0; off>>=1){
        e += __shfl_xor_sync(0xffffffffu, e, off);
        f += __shfl_xor_sync(0xffffffffu, f, off);
        c += __shfl_xor_sync(0xffffffffu, c, off);
    }
    if (t == 0 && out_size >= BSH + 3){
        out[BSH+0] = (float)(e / 65536.0);
        out[BSH+1] = (float)(f / 65536.0);
        out[BSH+2] = (float)(c / 65536.0);
    }
}

extern "C" void kernel_launch(void* const* d_in, const int* in_sizes, int n_in,
                              void* d_out, int out_size) {
    const float* hs   = (const float*)d_in[0];
    const float* gov  = (const float*)d_in[1];
    const float* Wq   = (const float*)d_in[2];
    const float* bq   = (const float*)d_in[3];
    const float* Wk   = (const float*)d_in[4];
    const float* bk   = (const float*)d_in[5];
    const float* Wv   = (const float*)d_in[6];
    const float* bv   = (const float*)d_in[7];
    const float* Wgq  = (const float*)d_in[8];
    const float* bgq  = (const float*)d_in[9];
    const float* Wgk  = (const float*)d_in[10];
    const float* bgk  = (const float*)d_in[11];
    float* out = (float*)d_out;

    init_kernel<<<1, 96>>>();
    proj_kernel<<<dim3(H_/128, B_*S_/128, 3), 256>>>(hs, Wq, bq, Wk, bk, Wv, bv);
    gq_kernel<<<dim3(H_/256, B_), 256>>>(gov, Wgq, bgq);
    u_kernel<<<(B_*H_*NH_)/256, 256>>>(Wgk);
    c_kernel<<<1, 32>>>(bgk);
    gov_kernel<<<B_*S_, 128>>>(hs);
    cudaFuncSetAttribute(flash_kernel, cudaFuncAttributeMaxDynamicSharedMemorySize, FLASH_SMEM);
    flash_kernel<<<dim3(S_/128, NH_, B_), 256, FLASH_SMEM>>>(out);
    fin_kernel<<<1, 32>>>(out, out_size);
}

// round 12
// speedup vs baseline: 1.3050x; 1.2173x over previous
#include <cuda_runtime.h>
#include <cuda_bf16.h>
#include <math.h>
#include <stdint.h>

#define B_   2
#define S_   2048
#define H_   1024
#define NH_  16
#define HD_  64
#define BSH  (B_*S_*H_)

typedef unsigned long long u64;

// ---------------- f32x2 helpers (flash kernel) ------------------------------
__device__ __forceinline__ u64 bcast2(float x){
    u64 r; asm("mov.b64 %0, {%1, %1};" : "=l"(r) : "f"(x)); return r;
}
__device__ __forceinline__ u64 pack2(float x, float y){
    u64 r; asm("mov.b64 %0, {%1, %2};" : "=l"(r) : "f"(x), "f"(y)); return r;
}
__device__ __forceinline__ float2 unpk(u64 a){
    float2 v; asm("mov.b64 {%0, %1}, %2;" : "=f"(v.x), "=f"(v.y) : "l"(a)); return v;
}
__device__ __forceinline__ u64 ffma2(u64 a, u64 b, u64 c){
    u64 d; asm("fma.rn.f32x2 %0, %1, %2, %3;" : "=l"(d) : "l"(a), "l"(b), "l"(c)); return d;
}
__device__ __forceinline__ u64 fmul2(u64 a, u64 b){
    u64 d; asm("mul.rn.f32x2 %0, %1, %2;" : "=l"(d) : "l"(a), "l"(b)); return d;
}

// ---------------- mma.sync helpers (portable tensor path, sm_80+) ------------
__device__ __forceinline__ uint32_t smem_to_u32(const void* p){
    uint32_t a;
    asm("{ .reg .u64 t; cvta.to.shared.u64 t, %1; cvt.u32.u64 %0, t; }" : "=r"(a) : "l"(p));
    return a;
}
__device__ __forceinline__ void ldsm_x4(uint32_t* r, uint32_t addr){
    asm volatile("ldmatrix.sync.aligned.m8n8.x4.shared.b16 {%0,%1,%2,%3}, [%4];"
        : "=r"(r[0]),"=r"(r[1]),"=r"(r[2]),"=r"(r[3]) : "r"(addr));
}
__device__ __forceinline__ void ldsm_x2(uint32_t* r, uint32_t addr){
    asm volatile("ldmatrix.sync.aligned.m8n8.x2.shared.b16 {%0,%1}, [%2];"
        : "=r"(r[0]),"=r"(r[1]) : "r"(addr));
}
__device__ __forceinline__ void mma_bf16(float* d, const uint32_t* a, const uint32_t* b){
    asm volatile("mma.sync.aligned.m16n8k16.row.col.f32.bf16.bf16.f32 "
        "{%0,%1,%2,%3}, {%4,%5,%6,%7}, {%8,%9}, {%0,%1,%2,%3};"
        : "+f"(d[0]),"+f"(d[1]),"+f"(d[2]),"+f"(d[3])
        : "r"(a[0]),"r"(a[1]),"r"(a[2]),"r"(a[3]), "r"(b[0]),"r"(b[1]));
}

// ---------------- device scratch --------------------------------------------
__device__ float g_Qt[B_*NH_*HD_*S_];   // [b][h][d][s], scaled by 1/8
__device__ float g_Kt[B_*NH_*HD_*S_];   // [b][h][d][s]
__device__ float g_V [B_*NH_*S_*HD_];   // [b][h][s][d]
__device__ float g_gq[B_*H_];
__device__ float g_u [B_*H_*NH_];
__device__ float g_c [B_*NH_];
__device__ double g_red[3][32];
__device__ __nv_bfloat16 g_Ahi[B_*S_*H_];       // hs split hi [m][k]
__device__ __nv_bfloat16 g_Alo[B_*S_*H_];       // hs split lo
__device__ __nv_bfloat16 g_WThi[3*H_*H_];       // W^T split hi [mode][n][k]
__device__ __nv_bfloat16 g_WTlo[3*H_*H_];

__global__ void init_kernel() {
    int t = threadIdx.x;
    if (t < 96) ((double*)g_red)[t] = 0.0;
}

// ---------------- split hs into bf16 hi/lo ----------------------------------
__global__ void split_hs_kernel(const float* __restrict__ hs)
{
    int row = blockIdx.x;
    int c = threadIdx.x * 4;
    float4 v = *(const float4*)(hs + (size_t)row*H_ + c);
    __nv_bfloat16 h0=__float2bfloat16_rn(v.x), h1=__float2bfloat16_rn(v.y),
                  h2=__float2bfloat16_rn(v.z), h3=__float2bfloat16_rn(v.w);
    __nv_bfloat16 l0=__float2bfloat16_rn(v.x-__bfloat162float(h0));
    __nv_bfloat16 l1=__float2bfloat16_rn(v.y-__bfloat162float(h1));
    __nv_bfloat16 l2=__float2bfloat16_rn(v.z-__bfloat162float(h2));
    __nv_bfloat16 l3=__float2bfloat16_rn(v.w-__bfloat162float(h3));
    ushort4 ph, pl;
    ph.x=*(unsigned short*)&h0; ph.y=*(unsigned short*)&h1;
    ph.z=*(unsigned short*)&h2; ph.w=*(unsigned short*)&h3;
    pl.x=*(unsigned short*)&l0; pl.y=*(unsigned short*)&l1;
    pl.z=*(unsigned short*)&l2; pl.w=*(unsigned short*)&l3;
    *(ushort4*)(g_Ahi + (size_t)row*H_ + c) = ph;
    *(ushort4*)(g_Alo + (size_t)row*H_ + c) = pl;
}

// ---------------- transpose + split W into bf16 WT[n][k] hi/lo --------------
__global__ void split_wT_kernel(const float* __restrict__ Wq,
                                const float* __restrict__ Wk,
                                const float* __restrict__ Wv)
{
    __shared__ float t[64][65];
    int mode = blockIdx.z;
    const float* W = mode==0 ? Wq : (mode==1 ? Wk : Wv);
    int k0 = blockIdx.x*64, n0 = blockIdx.y*64;
    int tid = threadIdx.x;
    #pragma unroll
    for (int i=0;i<4;i++){
        int idx = tid + i*256;
        int r = idx >> 4, c4 = (idx & 15) * 4;
        float4 v = *(const float4*)(W + (size_t)(k0+r)*H_ + n0 + c4);
        t[r][c4+0]=v.x; t[r][c4+1]=v.y; t[r][c4+2]=v.z; t[r][c4+3]=v.w;
    }
    __syncthreads();
    __nv_bfloat16* oh = g_WThi + (size_t)mode*H_*H_;
    __nv_bfloat16* ol = g_WTlo + (size_t)mode*H_*H_;
    #pragma unroll
    for (int i=0;i<4;i++){
        int idx = tid + i*256;
        int r = idx >> 4, c4 = (idx & 15) * 4;   // r = n-local, c4 = k-local
        float x0=t[c4+0][r], x1=t[c4+1][r], x2=t[c4+2][r], x3=t[c4+3][r];
        __nv_bfloat16 h0=__float2bfloat16_rn(x0), h1=__float2bfloat16_rn(x1),
                      h2=__float2bfloat16_rn(x2), h3=__float2bfloat16_rn(x3);
        __nv_bfloat16 l0=__float2bfloat16_rn(x0-__bfloat162float(h0));
        __nv_bfloat16 l1=__float2bfloat16_rn(x1-__bfloat162float(h1));
        __nv_bfloat16 l2=__float2bfloat16_rn(x2-__bfloat162float(h2));
        __nv_bfloat16 l3=__float2bfloat16_rn(x3-__bfloat162float(h3));
        ushort4 ph, pl;
        ph.x=*(unsigned short*)&h0; ph.y=*(unsigned short*)&h1;
        ph.z=*(unsigned short*)&h2; ph.w=*(unsigned short*)&h3;
        pl.x=*(unsigned short*)&l0; pl.y=*(unsigned short*)&l1;
        pl.z=*(unsigned short*)&l2; pl.w=*(unsigned short*)&l3;
        *(ushort4*)(oh + (size_t)(n0+r)*H_ + k0 + c4) = ph;
        *(ushort4*)(ol + (size_t)(n0+r)*H_ + k0 + c4) = pl;
    }
}

// ---------------- mma.sync split-bf16 projection GEMM ------------------------
// C[128m x 128n] = A @ W; A[m][k] row-major, B = WT[n][k] ("col" operand).
// 8 warps: warpM = wid&3 (32 rows each), warpN = wid>>2 (64 cols each).
#define PLD 72                          // smem row stride in bf16 (144 B)
#define PROJ_SMEM (4*128*PLD*2)         // Ah, Al, Bh, Bl  = 73728 B

__global__ void __launch_bounds__(256,1) projmm_kernel(
    const float* __restrict__ bq, const float* __restrict__ bk,
    const float* __restrict__ bv)
{
    extern __shared__ __nv_bfloat16 sm2[];
    __nv_bfloat16* sAh = sm2;
    __nv_bfloat16* sAl = sm2 + 128*PLD;
    __nv_bfloat16* sBh = sm2 + 2*128*PLD;
    __nv_bfloat16* sBl = sm2 + 3*128*PLD;
    uint32_t uAh = smem_to_u32(sAh), uAl = smem_to_u32(sAl);
    uint32_t uBh = smem_to_u32(sBh), uBl = smem_to_u32(sBl);

    int tid = threadIdx.x, wid = tid >> 5, lane = tid & 31;
    int warpM = wid & 3, warpN = wid >> 2;
    int mode = blockIdx.z, m0 = blockIdx.y*128, n0 = blockIdx.x*128;
    const __nv_bfloat16 *Ah = g_Ahi, *Al = g_Alo;
    const __nv_bfloat16 *Bh = g_WThi + (size_t)mode*H_*H_;
    const __nv_bfloat16 *Bl = g_WTlo + (size_t)mode*H_*H_;
    const float* bias = mode==0 ? bq : (mode==1 ? bk : bv);

    float acc[2][8][4];
    #pragma unroll
    for (int mi=0;mi<2;mi++)
        #pragma unroll
        for (int ni=0;ni<8;ni++)
            #pragma unroll
            for (int r=0;r<4;r++) acc[mi][ni][r] = 0.f;

    // ldmatrix per-lane row/col offsets
    int arow = (lane & 7) | (lane & 8);          // A: 0-7,8-15,0-7,8-15
    int akof = (lane & 16) ? 8 : 0;              // A: k +8 for lanes 16-31
    int brow = lane & 7;                         // B: n row 0-7
    int bkof = (lane & 8) ? 8 : 0;               // B: k +8 for lanes 8-15

    for (int kc = 0; kc < 16; kc++){
        __syncthreads();
        #pragma unroll
        for (int i=0;i<8;i++){
            int idx = tid + i*256;               // 0..2047
            int row = idx >> 4, kq = (idx & 15) * 4;
            size_t ga = (size_t)(m0+row)*H_ + kc*64 + kq;
            size_t gb = (size_t)(n0+row)*H_ + kc*64 + kq;
            int so = row*PLD + kq;
            *(u64*)(sAh + so) = *(const u64*)(Ah + ga);
            *(u64*)(sAl + so) = *(const u64*)(Al + ga);
            *(u64*)(sBh + so) = *(const u64*)(Bh + gb);
            *(u64*)(sBl + so) = *(const u64*)(Bl + gb);
        }
        __syncthreads();

        #pragma unroll
        for (int ks=0; ks<4; ks++){
            uint32_t ah[2][4], al[2][4], bh[8][2], bl[8][2];
            #pragma unroll
            for (int mi=0;mi<2;mi++){
                uint32_t off = (uint32_t)(((warpM*32 + mi*16 + arow)*PLD + ks*16 + akof) * 2);
                ldsm_x4(ah[mi], uAh + off);
                ldsm_x4(al[mi], uAl + off);
            }
            #pragma unroll
            for (int ni=0;ni<8;ni++){
                uint32_t off = (uint32_t)(((warpN*64 + ni*8 + brow)*PLD + ks*16 + bkof) * 2);
                ldsm_x2(bh[ni], uBh + off);
                ldsm_x2(bl[ni], uBl + off);
            }
            #pragma unroll
            for (int mi=0;mi<2;mi++)
                #pragma unroll
                for (int ni=0;ni<8;ni++){
                    mma_bf16(acc[mi][ni], ah[mi], bh[ni]);
                    mma_bf16(acc[mi][ni], ah[mi], bl[ni]);
                    mma_bf16(acc[mi][ni], al[mi], bh[ni]);
                }
        }
    }

    // bias preload: 16 values along this thread's n columns
    float bval[8][2];
    #pragma unroll
    for (int ni=0;ni<8;ni++)
        #pragma unroll
        for (int c=0;c<2;c++)
            bval[ni][c] = __ldg(bias + n0 + warpN*64 + ni*8 + (lane&3)*2 + c);

    if (mode < 2){
        float scale = (mode==0) ? 0.125f : 1.0f;
        float* dst = (mode==0) ? g_Qt : g_Kt;
        #pragma unroll
        for (int mi=0;mi<2;mi++)
            #pragma unroll
            for (int rg=0;rg<2;rg++){
                int m = m0 + warpM*32 + mi*16 + (lane>>2) + rg*8;
                int bidx = m >> 11, s = m & 2047;
                #pragma unroll
                for (int ni=0;ni<8;ni++)
                    #pragma unroll
                    for (int c=0;c<2;c++){
                        int n = n0 + warpN*64 + ni*8 + (lane&3)*2 + c;
                        int h = n >> 6, d = n & 63;
                        float v = (acc[mi][ni][rg*2+c] + bval[ni][c]) * scale;
                        dst[(((size_t)(bidx*NH_+h)*HD_ + d) << 11) + s] = v;
                    }
            }
    } else {
        #pragma unroll
        for (int mi=0;mi<2;mi++)
            #pragma unroll
            for (int rg=0;rg<2;rg++){
                int m = m0 + warpM*32 + mi*16 + (lane>>2) + rg*8;
                int bidx = m >> 11, s = m & 2047;
                #pragma unroll
                for (int ni=0;ni<8;ni++)
                    #pragma unroll
                    for (int c=0;c<2;c++){
                        int n = n0 + warpN*64 + ni*8 + (lane&3)*2 + c;
                        int h = n >> 6, d = n & 63;
                        float v = acc[mi][ni][rg*2+c] + bval[ni][c];
                        g_V[(((size_t)(bidx*NH_+h)*S_ + s) << 6) + d] = v;
                    }
            }
    }
}

// ---------------- governance small kernels ----------------------------------
__global__ void gq_kernel(const float* __restrict__ gov,
                          const float* __restrict__ Wgq,
                          const float* __restrict__ bgq)
{
    __shared__ float sg[H_];
    int b = blockIdx.y;
    int n = blockIdx.x*256 + threadIdx.x;
    for (int i=threadIdx.x; i<H_/4; i+=256)
        *(float4*)&sg[i*4] = *(const float4*)(gov + b*H_ + i*4);
    __syncthreads();
    float acc = 0.f;
    for (int k=0;k<H_;k++)
        acc += sg[k] * Wgq[(size_t)k*H_ + n];
    g_gq[b*H_ + n] = acc + bgq[n];
}

__global__ void u_kernel(const float* __restrict__ Wgk)
{
    int idx = blockIdx.x*256 + threadIdx.x;
    int h = idx & 15;
    int k = (idx >> 4) & 1023;
    int b = idx >> 14;
    const float* wrow = Wgk + (size_t)k*H_ + h*HD_;
    const float* gq   = g_gq + b*H_ + h*HD_;
    float acc = 0.f;
    #pragma unroll
    for (int d=0; d<HD_; d+=4){
        float4 w = *(const float4*)(wrow + d);
        float4 g = *(const float4*)(gq + d);
        acc += w.x*g.x + w.y*g.y + w.z*g.z + w.w*g.w;
    }
    g_u[idx] = acc;
}

__global__ void c_kernel(const float* __restrict__ bgk)
{
    int t = threadIdx.x;
    if (t < 32){
        int b = t >> 4, h = t & 15;
        const float* gq = g_gq + b*H_ + h*HD_;
        const float* bp = bgk + h*HD_;
        float acc = 0.f;
        #pragma unroll
        for (int d=0;d<HD_;d++) acc += bp[d]*gq[d];
        g_c[t] = acc;
    }
}

__global__ void gov_kernel(const float* __restrict__ hs)
{
    __shared__ float shs[H_];
    __shared__ float sred[4][16];
    int bs_ = blockIdx.x;
    int b = bs_ >> 11;
    int tid = threadIdx.x;   // 128
    const float* row = hs + (size_t)bs_ * H_;
    for (int i=tid; i<H_/4; i+=128)
        *(float4*)&shs[i*4] = *(const float4*)(row + i*4);
    __syncthreads();
    float acc[16];
    #pragma unroll
    for (int h=0;h<16;h++) acc[h]=0.f;
    const float* ub = g_u + b*16384;
    #pragma unroll
    for (int kk=0;kk<8;kk++){
        int k = kk*128 + tid;
        float hv = shs[k];
        const float* up = ub + k*16;
        #pragma unroll
        for (int h4=0; h4<4; h4++){
            float4 u4 = *(const float4*)(up + h4*4);
            acc[h4*4+0] += hv*u4.x;
            acc[h4*4+1] += hv*u4.y;
            acc[h4*4+2] += hv*u4.z;
            acc[h4*4+3] += hv*u4.w;
        }
    }
    #pragma unroll
    for (int h=0;h<16;h++){
        #pragma unroll
        for (int off=16; off>0; off>>=1)
            acc[h] += __shfl_xor_sync(0xffffffffu, acc[h], off);
    }
    int warp = tid>>5, lane = tid&31;
    if (lane==0){
        #pragma unroll
        for (int h=0;h<16;h++) sred[warp][h] = acc[h];
    }
    __syncthreads();
    if (tid < 16){
        float g = sred[0][tid]+sred[1][tid]+sred[2][tid]+sred[3][tid] + g_c[b*16+tid];
        float v = fabsf(g);
        #pragma unroll
        for (int off=8; off>0; off>>=1)
            v += __shfl_xor_sync(0xffffu, v, off);
        if (tid==0) atomicAdd(&g_red[1][bs_ & 31], (double)v);
    }
}

// ---------------- flash attention (f32x2 version, proven) --------------------
#define FLASH_SMEM ((2*64*132 + 128*68 + 128*132)*4)

__global__ void __launch_bounds__(256,1) flash_kernel(float* __restrict__ out)
{
    extern __shared__ float sm[];
    float* sQT = sm;
    float* sKT = sm + 64*132;
    float* sV  = sm + 2*64*132;
    float* sPT = sV + 128*68;

    int q0 = blockIdx.x * 128;
    int h  = blockIdx.y;
    int b  = blockIdx.z;
    const float* Qbh = g_Qt + (size_t)(b*NH_+h)*HD_*S_;
    const float* Kbh = g_Kt + (size_t)(b*NH_+h)*HD_*S_;
    const float* Vbh = g_V  + (size_t)(b*NH_+h)*S_*HD_;

    int tid = threadIdx.x, warp = tid >> 5, lane = tid & 31;
    int lr = lane >> 4, lc = lane & 15;
    int rowBase = warp*16 + lr*4;
    int colV = lc*4;

    for (int g = tid; g < 64*32; g += 256){
        int d = g >> 5, c = (g & 31) << 2;
        *(float4*)&sQT[d*132 + c] = *(const float4*)(Qbh + (size_t)d*S_ + q0 + c);
    }

    u64 oacc2[4][4];
    float mrow[8], lrow[8], trow[8];
    #pragma unroll
    for (int i=0;i<8;i++){ mrow[i] = -1e30f; lrow[i] = 0.f; trow[i] = 0.f; }
    #pragma unroll
    for (int i=0;i<4;i++)
        #pragma unroll
        for (int c=0;c<4;c++) oacc2[i][c] = 0ull;

    for (int j0 = 0; j0 < S_; j0 += 128){
        __syncthreads();
        for (int g = tid; g < 64*32; g += 256){
            int d = g >> 5, c = (g & 31) << 2;
            *(float4*)&sKT[d*132 + c] = *(const float4*)(Kbh + (size_t)d*S_ + j0 + c);
        }
        for (int g = tid; g < 128*16; g += 256){
            int j = g >> 4, dv = (g & 15) << 2;
            *(float4*)&sV[j*68 + dv] = *(const float4*)(Vbh + (size_t)(j0+j)*HD_ + dv);
        }
        __syncthreads();

        u64 sc2[4][8];
        #pragma unroll
        for (int i=0;i<4;i++)
            #pragma unroll
            for (int j=0;j<8;j++) sc2[i][j] = 0ull;
        #pragma unroll 4
        for (int d=0; d<64; d++){
            ulonglong2 A0 = *(ulonglong2*)&sQT[d*132 + rowBase];
            ulonglong2 A1 = *(ulonglong2*)&sQT[d*132 + rowBase + 8];
            u64 a2[4] = {A0.x, A0.y, A1.x, A1.y};
            float4 k0 = *(float4*)&sKT[d*132 + lc*4];
            float4 k1 = *(float4*)&sKT[d*132 + lc*4 + 64];
            u64 b2[8];
            b2[0]=bcast2(k0.x); b2[1]=bcast2(k0.y); b2[2]=bcast2(k0.z); b2[3]=bcast2(k0.w);
            b2[4]=bcast2(k1.x); b2[5]=bcast2(k1.y); b2[6]=bcast2(k1.z); b2[7]=bcast2(k1.w);
            #pragma unroll
            for (int i=0;i<4;i++)
                #pragma unroll
                for (int j=0;j<8;j++)
                    sc2[i][j] = ffma2(a2[i], b2[j], sc2[i][j]);
        }

        float sc_[8][8];
        #pragma unroll
        for (int i2=0;i2<4;i2++)
            #pragma unroll
            for (int j=0;j<8;j++){
                float2 v = unpk(sc2[i2][j]);
                sc_[2*i2][j] = v.x; sc_[2*i2+1][j] = v.y;
            }

        float scl8[8];
        #pragma unroll
        for (int i=0;i<8;i++){
            float tm = sc_[i][0];
            #pragma unroll
            for (int j=1;j<8;j++) tm = fmaxf(tm, sc_[i][j]);
            #pragma unroll
            for (int off=8; off>0; off>>=1)
                tm = fmaxf(tm, __shfl_xor_sync(0xffffffffu, tm, off));
            float mn = fmaxf(mrow[i], tm);
            float la = 0.f, ta = 0.f;
            #pragma unroll
            for (int j=0;j<8;j++){
                float s = sc_[i][j];
                float e = __expf(s - mn);
                sc_[i][j] = e;
                la += e;
                ta += e*s;
            }
            #pragma unroll
            for (int off=8; off>0; off>>=1){
                la += __shfl_xor_sync(0xffffffffu, la, off);
                ta += __shfl_xor_sync(0xffffffffu, ta, off);
            }
            float scl = __expf(mrow[i]-mn);
            lrow[i] = lrow[i]*scl + la;
            trow[i] = trow[i]*scl + ta;
            mrow[i] = mn;
            scl8[i] = scl;
        }
        #pragma unroll
        for (int i2=0;i2<4;i2++){
            u64 sp = pack2(scl8[2*i2], scl8[2*i2+1]);
            #pragma unroll
            for (int c=0;c<4;c++) oacc2[i2][c] = fmul2(oacc2[i2][c], sp);
        }

        #pragma unroll
        for (int j=0;j<8;j++){
            int cc = lc*4 + j + ((j>=4)?60:0);
            float4 v0 = make_float4(sc_[0][j],sc_[1][j],sc_[2][j],sc_[3][j]);
            float4 v1 = make_float4(sc_[4][j],sc_[5][j],sc_[6][j],sc_[7][j]);
            *(float4*)&sPT[cc*132 + rowBase]     = v0;
            *(float4*)&sPT[cc*132 + rowBase + 8] = v1;
        }
        __syncthreads();

        #pragma unroll 4
        for (int j=0;j<128;j++){
            ulonglong2 P0 = *(ulonglong2*)&sPT[j*132 + rowBase];
            ulonglong2 P1 = *(ulonglong2*)&sPT[j*132 + rowBase + 8];
            u64 p2[4] = {P0.x, P0.y, P1.x, P1.y};
            float4 vv = *(float4*)&sV[j*68 + colV];
            u64 v2[4] = {bcast2(vv.x), bcast2(vv.y), bcast2(vv.z), bcast2(vv.w)};
            #pragma unroll
            for (int i=0;i<4;i++)
                #pragma unroll
                for (int c=0;c<4;c++)
                    oacc2[i][c] = ffma2(p2[i], v2[c], oacc2[i][c]);
        }
    }

    float accf[8][4];
    #pragma unroll
    for (int i2=0;i2<4;i2++)
        #pragma unroll
        for (int c=0;c<4;c++){
            float2 v = unpk(oacc2[i2][c]);
            accf[2*i2][c] = v.x; accf[2*i2+1][c] = v.y;
        }

    #pragma unroll
    for (int i=0;i<8;i++){
        int r = rowBase + i + ((i>=4)?4:0);
        float inv = 1.0f / lrow[i];
        float4 v = make_float4(accf[i][0]*inv, accf[i][1]*inv,
                               accf[i][2]*inv, accf[i][3]*inv);
        *(float4*)(out + ((size_t)b*S_ + (q0+r))*H_ + h*HD_ + colV) = v;
    }
    if (lc == 0){
        double es = 0.0, cs = 0.0;
        #pragma unroll
        for (int i=0;i<8;i++){
            es += (double)(mrow[i] + logf(lrow[i]) - trow[i]/lrow[i] - 2.048e-5f);
            cs += (double)(1.0f / lrow[i]);
        }
        atomicAdd(&g_red[0][tid & 31], es);
        atomicAdd(&g_red[2][tid & 31], cs);
    }
}

__global__ void fin_kernel(float* __restrict__ out, int out_size)
{
    int t = threadIdx.x;  // 32
    double e = g_red[0][t], f = g_red[1][t], c = g_red[2][t];
    #pragma unroll
    for (int off=16; off>0; off>>=1){
        e += __shfl_xor_sync(0xffffffffu, e, off);
        f += __shfl_xor_sync(0xffffffffu, f, off);
        c += __shfl_xor_sync(0xffffffffu, c, off);
    }
    if (t == 0 && out_size >= BSH + 3){
        out[BSH+0] = (float)(e / 65536.0);
        out[BSH+1] = (float)(f / 65536.0);
        out[BSH+2] = (float)(c / 65536.0);
    }
}

extern "C" void kernel_launch(void* const* d_in, const int* in_sizes, int n_in,
                              void* d_out, int out_size) {
    const float* hs   = (const float*)d_in[0];
    const float* gov  = (const float*)d_in[1];
    const float* Wq   = (const float*)d_in[2];
    const float* bq   = (const float*)d_in[3];
    const float* Wk   = (const float*)d_in[4];
    const float* bk   = (const float*)d_in[5];
    const float* Wv   = (const float*)d_in[6];
    const float* bv   = (const float*)d_in[7];
    const float* Wgq  = (const float*)d_in[8];
    const float* bgq  = (const float*)d_in[9];
    const float* Wgk  = (const float*)d_in[10];
    const float* bgk  = (const float*)d_in[11];
    float* out = (float*)d_out;

    init_kernel<<<1, 96>>>();
    split_hs_kernel<<<B_*S_, 256>>>(hs);
    split_wT_kernel<<<dim3(16, 16, 3), 256>>>(Wq, Wk, Wv);
    cudaFuncSetAttribute(projmm_kernel, cudaFuncAttributeMaxDynamicSharedMemorySize, PROJ_SMEM);
    projmm_kernel<<<dim3(H_/128, B_*S_/128, 3), 256, PROJ_SMEM>>>(bq, bk, bv);
    gq_kernel<<<dim3(H_/256, B_), 256>>>(gov, Wgq, bgq);
    u_kernel<<<(B_*H_*NH_)/256, 256>>>(Wgk);
    c_kernel<<<1, 32>>>(bgk);
    gov_kernel<<<B_*S_, 128>>>(hs);
    cudaFuncSetAttribute(flash_kernel, cudaFuncAttributeMaxDynamicSharedMemorySize, FLASH_SMEM);
    flash_kernel<<<dim3(S_/128, NH_, B_), 256, FLASH_SMEM>>>(out);
    fin_kernel<<<1, 32>>>(out, out_size);
}

// round 13
// speedup vs baseline: 2.2098x; 1.6933x over previous
#include <cuda_runtime.h>
#include <cuda_bf16.h>
#include <math.h>
#include <stdint.h>

#define B_   2
#define S_   2048
#define H_   1024
#define NH_  16
#define HD_  64
#define BSH  (B_*S_*H_)

typedef unsigned long long u64;

// ---------------- mma.sync helpers (sm_80+ portable tensor path) -------------
__device__ __forceinline__ uint32_t smem_to_u32(const void* p){
    uint32_t a;
    asm("{ .reg .u64 t; cvta.to.shared.u64 t, %1; cvt.u32.u64 %0, t; }" : "=r"(a) : "l"(p));
    return a;
}
__device__ __forceinline__ void ldsm_x4(uint32_t* r, uint32_t addr){
    asm volatile("ldmatrix.sync.aligned.m8n8.x4.shared.b16 {%0,%1,%2,%3}, [%4];"
        : "=r"(r[0]),"=r"(r[1]),"=r"(r[2]),"=r"(r[3]) : "r"(addr));
}
__device__ __forceinline__ void ldsm_x2(uint32_t* r, uint32_t addr){
    asm volatile("ldmatrix.sync.aligned.m8n8.x2.shared.b16 {%0,%1}, [%2];"
        : "=r"(r[0]),"=r"(r[1]) : "r"(addr));
}
__device__ __forceinline__ void mma_bf16(float* d, const uint32_t* a, const uint32_t* b){
    asm volatile("mma.sync.aligned.m16n8k16.row.col.f32.bf16.bf16.f32 "
        "{%0,%1,%2,%3}, {%4,%5,%6,%7}, {%8,%9}, {%0,%1,%2,%3};"
        : "+f"(d[0]),"+f"(d[1]),"+f"(d[2]),"+f"(d[3])
        : "r"(a[0]),"r"(a[1]),"r"(a[2]),"r"(a[3]), "r"(b[0]),"r"(b[1]));
}
// pack two floats -> bf16x2 {lo, hi} with rn
__device__ __forceinline__ uint32_t packbf2(float lo, float hi){
    uint32_t r; asm("cvt.rn.bf16x2.f32 %0, %1, %2;" : "=r"(r) : "f"(hi), "f"(lo)); return r;
}
__device__ __forceinline__ float bf2lo(uint32_t p){ return __uint_as_float(p << 16); }
__device__ __forceinline__ float bf2hi(uint32_t p){ return __uint_as_float(p & 0xffff0000u); }

// ---------------- device scratch --------------------------------------------
__device__ __nv_bfloat16 g_Qhi[B_*NH_*S_*HD_];   // [b][h][s][d] scaled
__device__ __nv_bfloat16 g_Qlo[B_*NH_*S_*HD_];
__device__ __nv_bfloat16 g_Khi[B_*NH_*S_*HD_];   // [b][h][s][d]
__device__ __nv_bfloat16 g_Klo[B_*NH_*S_*HD_];
__device__ __nv_bfloat16 g_VThi[B_*NH_*HD_*S_];  // [b][h][d][s]
__device__ __nv_bfloat16 g_VTlo[B_*NH_*HD_*S_];
__device__ float g_gq[B_*H_];
__device__ float g_u [B_*H_*NH_];
__device__ float g_c [B_*NH_];
__device__ double g_red[3][32];
__device__ __nv_bfloat16 g_Ahi[B_*S_*H_];       // hs split hi [m][k]
__device__ __nv_bfloat16 g_Alo[B_*S_*H_];
__device__ __nv_bfloat16 g_WThi[3*H_*H_];       // W^T split hi [mode][n][k]
__device__ __nv_bfloat16 g_WTlo[3*H_*H_];

__global__ void init_kernel() {
    int t = threadIdx.x;
    if (t < 96) ((double*)g_red)[t] = 0.0;
}

// ---------------- split hs into bf16 hi/lo ----------------------------------
__global__ void split_hs_kernel(const float* __restrict__ hs)
{
    int row = blockIdx.x;
    int c = threadIdx.x * 4;
    float4 v = *(const float4*)(hs + (size_t)row*H_ + c);
    uint32_t p0 = packbf2(v.x, v.y), p1 = packbf2(v.z, v.w);
    uint32_t l0 = packbf2(v.x - bf2lo(p0), v.y - bf2hi(p0));
    uint32_t l1 = packbf2(v.z - bf2lo(p1), v.w - bf2hi(p1));
    uint2 ph = make_uint2(p0, p1), pl = make_uint2(l0, l1);
    *(uint2*)(g_Ahi + (size_t)row*H_ + c) = ph;
    *(uint2*)(g_Alo + (size_t)row*H_ + c) = pl;
}

// ---------------- transpose + split W into bf16 WT[n][k] hi/lo --------------
__global__ void split_wT_kernel(const float* __restrict__ Wq,
                                const float* __restrict__ Wk,
                                const float* __restrict__ Wv)
{
    __shared__ float t[64][65];
    int mode = blockIdx.z;
    const float* W = mode==0 ? Wq : (mode==1 ? Wk : Wv);
    int k0 = blockIdx.x*64, n0 = blockIdx.y*64;
    int tid = threadIdx.x;
    #pragma unroll
    for (int i=0;i<4;i++){
        int idx = tid + i*256;
        int r = idx >> 4, c4 = (idx & 15) * 4;
        float4 v = *(const float4*)(W + (size_t)(k0+r)*H_ + n0 + c4);
        t[r][c4+0]=v.x; t[r][c4+1]=v.y; t[r][c4+2]=v.z; t[r][c4+3]=v.w;
    }
    __syncthreads();
    __nv_bfloat16* oh = g_WThi + (size_t)mode*H_*H_;
    __nv_bfloat16* ol = g_WTlo + (size_t)mode*H_*H_;
    #pragma unroll
    for (int i=0;i<4;i++){
        int idx = tid + i*256;
        int r = idx >> 4, c4 = (idx & 15) * 4;   // r = n-local, c4 = k-local
        float x0=t[c4+0][r], x1=t[c4+1][r], x2=t[c4+2][r], x3=t[c4+3][r];
        uint32_t p0 = packbf2(x0, x1), p1 = packbf2(x2, x3);
        uint32_t l0 = packbf2(x0 - bf2lo(p0), x1 - bf2hi(p0));
        uint32_t l1 = packbf2(x2 - bf2lo(p1), x3 - bf2hi(p1));
        *(uint2*)(oh + (size_t)(n0+r)*H_ + k0 + c4) = make_uint2(p0, p1);
        *(uint2*)(ol + (size_t)(n0+r)*H_ + k0 + c4) = make_uint2(l0, l1);
    }
}

// ---------------- mma.sync split-bf16 projection GEMM ------------------------
#define PLD 72
#define PROJ_SMEM (4*128*PLD*2)

__global__ void __launch_bounds__(256,1) projmm_kernel(
    const float* __restrict__ bq, const float* __restrict__ bk,
    const float* __restrict__ bv)
{
    extern __shared__ __nv_bfloat16 sm2[];
    __nv_bfloat16* sAh = sm2;
    __nv_bfloat16* sAl = sm2 + 128*PLD;
    __nv_bfloat16* sBh = sm2 + 2*128*PLD;
    __nv_bfloat16* sBl = sm2 + 3*128*PLD;
    uint32_t uAh = smem_to_u32(sAh), uAl = smem_to_u32(sAl);
    uint32_t uBh = smem_to_u32(sBh), uBl = smem_to_u32(sBl);

    int tid = threadIdx.x, wid = tid >> 5, lane = tid & 31;
    int warpM = wid & 3, warpN = wid >> 2;
    int mode = blockIdx.z, m0 = blockIdx.y*128, n0 = blockIdx.x*128;
    const __nv_bfloat16 *Ah = g_Ahi, *Al = g_Alo;
    const __nv_bfloat16 *Bh = g_WThi + (size_t)mode*H_*H_;
    const __nv_bfloat16 *Bl = g_WTlo + (size_t)mode*H_*H_;
    const float* bias = mode==0 ? bq : (mode==1 ? bk : bv);

    float acc[2][8][4];
    #pragma unroll
    for (int mi=0;mi<2;mi++)
        #pragma unroll
        for (int ni=0;ni<8;ni++)
            #pragma unroll
            for (int r=0;r<4;r++) acc[mi][ni][r] = 0.f;

    int arow = lane & 15;
    int akof = (lane & 16) ? 8 : 0;
    int brow = lane & 7;
    int bkof = (lane & 8) ? 8 : 0;

    for (int kc = 0; kc < 16; kc++){
        __syncthreads();
        #pragma unroll
        for (int i=0;i<8;i++){
            int idx = tid + i*256;
            int row = idx >> 4, kq = (idx & 15) * 4;
            size_t ga = (size_t)(m0+row)*H_ + kc*64 + kq;
            size_t gb = (size_t)(n0+row)*H_ + kc*64 + kq;
            int so = row*PLD + kq;
            *(u64*)(sAh + so) = *(const u64*)(Ah + ga);
            *(u64*)(sAl + so) = *(const u64*)(Al + ga);
            *(u64*)(sBh + so) = *(const u64*)(Bh + gb);
            *(u64*)(sBl + so) = *(const u64*)(Bl + gb);
        }
        __syncthreads();

        #pragma unroll
        for (int ks=0; ks<4; ks++){
            uint32_t ah[2][4], al[2][4], bh[8][2], bl[8][2];
            #pragma unroll
            for (int mi=0;mi<2;mi++){
                uint32_t off = (uint32_t)(((warpM*32 + mi*16 + arow)*PLD + ks*16 + akof) * 2);
                ldsm_x4(ah[mi], uAh + off);
                ldsm_x4(al[mi], uAl + off);
            }
            #pragma unroll
            for (int ni=0;ni<8;ni++){
                uint32_t off = (uint32_t)(((warpN*64 + ni*8 + brow)*PLD + ks*16 + bkof) * 2);
                ldsm_x2(bh[ni], uBh + off);
                ldsm_x2(bl[ni], uBl + off);
            }
            #pragma unroll
            for (int mi=0;mi<2;mi++)
                #pragma unroll
                for (int ni=0;ni<8;ni++){
                    mma_bf16(acc[mi][ni], ah[mi], bh[ni]);
                    mma_bf16(acc[mi][ni], ah[mi], bl[ni]);
                    mma_bf16(acc[mi][ni], al[mi], bh[ni]);
                }
        }
    }

    float bval[8][2];
    #pragma unroll
    for (int ni=0;ni<8;ni++)
        #pragma unroll
        for (int c=0;c<2;c++)
            bval[ni][c] = __ldg(bias + n0 + warpN*64 + ni*8 + (lane&3)*2 + c);

    int hh = (n0 >> 6) + warpN;          // head is constant per warp
    if (mode < 2){
        float scale = (mode==0) ? 0.125f : 1.0f;
        __nv_bfloat16* dh = (mode==0) ? g_Qhi : g_Khi;
        __nv_bfloat16* dl = (mode==0) ? g_Qlo : g_Klo;
        #pragma unroll
        for (int mi=0;mi<2;mi++)
            #pragma unroll
            for (int rg=0;rg<2;rg++){
                int m = m0 + warpM*32 + mi*16 + (lane>>2) + rg*8;
                int bidx = m >> 11, s = m & 2047;
                size_t base = ((size_t)(bidx*NH_+hh)*S_ + s)*HD_;
                #pragma unroll
                for (int ni=0;ni<8;ni++){
                    float v0 = (acc[mi][ni][rg*2+0] + bval[ni][0]) * scale;
                    float v1 = (acc[mi][ni][rg*2+1] + bval[ni][1]) * scale;
                    uint32_t ph = packbf2(v0, v1);
                    uint32_t pl = packbf2(v0 - bf2lo(ph), v1 - bf2hi(ph));
                    int doff = ni*8 + (lane&3)*2;
                    *(uint32_t*)(dh + base + doff) = ph;
                    *(uint32_t*)(dl + base + doff) = pl;
                }
            }
    } else {
        #pragma unroll
        for (int mi=0;mi<2;mi++)
            #pragma unroll
            for (int rg=0;rg<2;rg++){
                int m = m0 + warpM*32 + mi*16 + (lane>>2) + rg*8;
                int bidx = m >> 11, s = m & 2047;
                size_t base = (size_t)(bidx*NH_+hh)*HD_*S_;
                #pragma unroll
                for (int ni=0;ni<8;ni++)
                    #pragma unroll
                    for (int c=0;c<2;c++){
                        int d = ni*8 + (lane&3)*2 + c;
                        float v = acc[mi][ni][rg*2+c] + bval[ni][c];
                        __nv_bfloat16 vh = __float2bfloat16_rn(v);
                        size_t vi = base + (size_t)d*S_ + s;
                        g_VThi[vi] = vh;
                        g_VTlo[vi] = __float2bfloat16_rn(v - __bfloat162float(vh));
                    }
            }
    }
}

// ---------------- governance small kernels ----------------------------------
__global__ void gq_kernel(const float* __restrict__ gov,
                          const float* __restrict__ Wgq,
                          const float* __restrict__ bgq)
{
    __shared__ float sg[H_];
    int b = blockIdx.y;
    int n = blockIdx.x*256 + threadIdx.x;
    for (int i=threadIdx.x; i<H_/4; i+=256)
        *(float4*)&sg[i*4] = *(const float4*)(gov + b*H_ + i*4);
    __syncthreads();
    float acc = 0.f;
    for (int k=0;k<H_;k++)
        acc += sg[k] * Wgq[(size_t)k*H_ + n];
    g_gq[b*H_ + n] = acc + bgq[n];
}

__global__ void u_kernel(const float* __restrict__ Wgk)
{
    int idx = blockIdx.x*256 + threadIdx.x;
    int h = idx & 15;
    int k = (idx >> 4) & 1023;
    int b = idx >> 14;
    const float* wrow = Wgk + (size_t)k*H_ + h*HD_;
    const float* gq   = g_gq + b*H_ + h*HD_;
    float acc = 0.f;
    #pragma unroll
    for (int d=0; d<HD_; d+=4){
        float4 w = *(const float4*)(wrow + d);
        float4 g = *(const float4*)(gq + d);
        acc += w.x*g.x + w.y*g.y + w.z*g.z + w.w*g.w;
    }
    g_u[idx] = acc;
}

__global__ void c_kernel(const float* __restrict__ bgk)
{
    int t = threadIdx.x;
    if (t < 32){
        int b = t >> 4, h = t & 15;
        const float* gq = g_gq + b*H_ + h*HD_;
        const float* bp = bgk + h*HD_;
        float acc = 0.f;
        #pragma unroll
        for (int d=0;d<HD_;d++) acc += bp[d]*gq[d];
        g_c[t] = acc;
    }
}

__global__ void gov_kernel(const float* __restrict__ hs)
{
    __shared__ float shs[H_];
    __shared__ float sred[4][16];
    int bs_ = blockIdx.x;
    int b = bs_ >> 11;
    int tid = threadIdx.x;   // 128
    const float* row = hs + (size_t)bs_ * H_;
    for (int i=tid; i<H_/4; i+=128)
        *(float4*)&shs[i*4] = *(const float4*)(row + i*4);
    __syncthreads();
    float acc[16];
    #pragma unroll
    for (int h=0;h<16;h++) acc[h]=0.f;
    const float* ub = g_u + b*16384;
    #pragma unroll
    for (int kk=0;kk<8;kk++){
        int k = kk*128 + tid;
        float hv = shs[k];
        const float* up = ub + k*16;
        #pragma unroll
        for (int h4=0; h4<4; h4++){
            float4 u4 = *(const float4*)(up + h4*4);
            acc[h4*4+0] += hv*u4.x;
            acc[h4*4+1] += hv*u4.y;
            acc[h4*4+2] += hv*u4.z;
            acc[h4*4+3] += hv*u4.w;
        }
    }
    #pragma unroll
    for (int h=0;h<16;h++){
        #pragma unroll
        for (int off=16; off>0; off>>=1)
            acc[h] += __shfl_xor_sync(0xffffffffu, acc[h], off);
    }
    int warp = tid>>5, lane = tid&31;
    if (lane==0){
        #pragma unroll
        for (int h=0;h<16;h++) sred[warp][h] = acc[h];
    }
    __syncthreads();
    if (tid < 16){
        float g = sred[0][tid]+sred[1][tid]+sred[2][tid]+sred[3][tid] + g_c[b*16+tid];
        float v = fabsf(g);
        #pragma unroll
        for (int off=8; off>0; off>>=1)
            v += __shfl_xor_sync(0xffffu, v, off);
        if (tid==0) atomicAdd(&g_red[1][bs_ & 31], (double)v);
    }
}

// ---------------- flash attention via mma.sync split-bf16 --------------------
// 8 warps x 16 q-rows; K [s][d] hi/lo -> B frags; V^T [d][s] hi/lo -> B frags.
// P fragments built in registers from S accumulators (FA-2 layout reuse).
#define KLD 72
#define VLD 136
#define FLASH_SMEM ((2*128*KLD + 2*64*VLD)*2)

__global__ void __launch_bounds__(256,1) flashmma_kernel(float* __restrict__ out)
{
    extern __shared__ __nv_bfloat16 fsm[];
    __nv_bfloat16* sKh = fsm;                 // [128][72]
    __nv_bfloat16* sKl = fsm + 128*KLD;
    __nv_bfloat16* sVh = fsm + 2*128*KLD;     // [64][136]
    __nv_bfloat16* sVl = sVh + 64*VLD;
    uint32_t uKh = smem_to_u32(sKh), uKl = smem_to_u32(sKl);
    uint32_t uVh = smem_to_u32(sVh), uVl = smem_to_u32(sVl);

    int q0 = blockIdx.x * 128;
    int h  = blockIdx.y;
    int b  = blockIdx.z;
    size_t bh = (size_t)(b*NH_ + h);
    const __nv_bfloat16* Qh_ = g_Qhi + bh*S_*HD_;
    const __nv_bfloat16* Ql_ = g_Qlo + bh*S_*HD_;
    const __nv_bfloat16* Kh_ = g_Khi + bh*S_*HD_;
    const __nv_bfloat16* Kl_ = g_Klo + bh*S_*HD_;
    const __nv_bfloat16* Vh_ = g_VThi + bh*HD_*S_;
    const __nv_bfloat16* Vl_ = g_VTlo + bh*HD_*S_;

    int tid = threadIdx.x, wid = tid >> 5, lane = tid & 31;
    int wrow = wid * 16;
    int arow = lane & 15;
    int akof = (lane & 16) ? 8 : 0;
    int brow = lane & 7;
    int bt = (lane >> 4) & 1;
    int bk = (lane >> 3) & 1;

    // stage Q tile into K smem buffers, build Q fragments
    #pragma unroll
    for (int i=0;i<4;i++){
        int idx = tid + i*256;                 // 1024 chunks of 8 bf16
        int row = idx >> 3, c8 = (idx & 7) * 8;
        *(uint4*)(sKh + row*KLD + c8) = *(const uint4*)(Qh_ + (size_t)(q0+row)*HD_ + c8);
        *(uint4*)(sKl + row*KLD + c8) = *(const uint4*)(Ql_ + (size_t)(q0+row)*HD_ + c8);
    }
    __syncthreads();
    uint32_t qh[4][4], ql[4][4];
    #pragma unroll
    for (int kt=0; kt<4; kt++){
        uint32_t off = (uint32_t)(((wrow + arow)*KLD + kt*16 + akof) * 2);
        ldsm_x4(qh[kt], uKh + off);
        ldsm_x4(ql[kt], uKl + off);
    }

    float o[8][4];
    #pragma unroll
    for (int ni=0;ni<8;ni++)
        #pragma unroll
        for (int r=0;r<4;r++) o[ni][r] = 0.f;
    float m0=-1e30f, m1=-1e30f, l0=0.f, l1=0.f, t0=0.f, t1=0.f;

    for (int j0 = 0; j0 < S_; j0 += 128){
        __syncthreads();
        #pragma unroll
        for (int i=0;i<4;i++){
            int idx = tid + i*256;
            int row = idx >> 3, c8 = (idx & 7) * 8;
            *(uint4*)(sKh + row*KLD + c8) = *(const uint4*)(Kh_ + (size_t)(j0+row)*HD_ + c8);
            *(uint4*)(sKl + row*KLD + c8) = *(const uint4*)(Kl_ + (size_t)(j0+row)*HD_ + c8);
        }
        #pragma unroll
        for (int i=0;i<4;i++){
            int idx = tid + i*256;                 // 1024 chunks
            int row = idx >> 4, c8 = (idx & 15) * 8;
            *(uint4*)(sVh + row*VLD + c8) = *(const uint4*)(Vh_ + (size_t)row*S_ + j0 + c8);
            *(uint4*)(sVl + row*VLD + c8) = *(const uint4*)(Vl_ + (size_t)row*S_ + j0 + c8);
        }
        __syncthreads();

        // S = Q K^T (scale in Q), warp tile 16x128
        float sc[16][4];
        #pragma unroll
        for (int t=0;t<16;t++)
            #pragma unroll
            for (int r=0;r<4;r++) sc[t][r] = 0.f;
        #pragma unroll
        for (int ks=0; ks<4; ks++){
            #pragma unroll
            for (int p=0;p<8;p++){
                uint32_t kh4[4], kl4[4];
                uint32_t off = (uint32_t)(((p*16 + bt*8 + brow)*KLD + ks*16 + bk*8) * 2);
                ldsm_x4(kh4, uKh + off);
                ldsm_x4(kl4, uKl + off);
                mma_bf16(sc[2*p],   qh[ks], &kh4[0]);
                mma_bf16(sc[2*p],   qh[ks], &kl4[0]);
                mma_bf16(sc[2*p],   ql[ks], &kh4[0]);
                mma_bf16(sc[2*p+1], qh[ks], &kh4[2]);
                mma_bf16(sc[2*p+1], qh[ks], &kl4[2]);
                mma_bf16(sc[2*p+1], ql[ks], &kh4[2]);
            }
        }

        // online softmax over 128 cols (rows r=lane>>2 and r+8)
        float mx0 = -1e30f, mx1 = -1e30f;
        #pragma unroll
        for (int t=0;t<16;t++){
            mx0 = fmaxf(mx0, fmaxf(sc[t][0], sc[t][1]));
            mx1 = fmaxf(mx1, fmaxf(sc[t][2], sc[t][3]));
        }
        #pragma unroll
        for (int off=1; off<4; off<<=1){
            mx0 = fmaxf(mx0, __shfl_xor_sync(0xffffffffu, mx0, off));
            mx1 = fmaxf(mx1, __shfl_xor_sync(0xffffffffu, mx1, off));
        }
        float mn0 = fmaxf(m0, mx0), mn1 = fmaxf(m1, mx1);
        float la0=0.f, ta0=0.f, la1=0.f, ta1=0.f;
        #pragma unroll
        for (int t=0;t<16;t++){
            float s0 = sc[t][0], s1 = sc[t][1], s2 = sc[t][2], s3 = sc[t][3];
            float e0 = __expf(s0-mn0), e1 = __expf(s1-mn0);
            float e2 = __expf(s2-mn1), e3 = __expf(s3-mn1);
            la0 += e0+e1; ta0 += e0*s0 + e1*s1;
            la1 += e2+e3; ta1 += e2*s2 + e3*s3;
            sc[t][0]=e0; sc[t][1]=e1; sc[t][2]=e2; sc[t][3]=e3;
        }
        #pragma unroll
        for (int off=1; off<4; off<<=1){
            la0 += __shfl_xor_sync(0xffffffffu, la0, off);
            ta0 += __shfl_xor_sync(0xffffffffu, ta0, off);
            la1 += __shfl_xor_sync(0xffffffffu, la1, off);
            ta1 += __shfl_xor_sync(0xffffffffu, ta1, off);
        }
        float scl0 = __expf(m0-mn0), scl1 = __expf(m1-mn1);
        l0 = l0*scl0 + la0; t0 = t0*scl0 + ta0; m0 = mn0;
        l1 = l1*scl1 + la1; t1 = t1*scl1 + ta1; m1 = mn1;
        #pragma unroll
        for (int ni=0;ni<8;ni++){
            o[ni][0]*=scl0; o[ni][1]*=scl0; o[ni][2]*=scl1; o[ni][3]*=scl1;
        }

        // O += P V  (P frags from accumulators, split hi/lo)
        #pragma unroll
        for (int kt=0; kt<8; kt++){
            uint32_t pa[4], pb[4];
            #pragma unroll
            for (int q=0;q<4;q++){
                int t = 2*kt + (q>>1);
                float x = sc[t][(q&1)*2+0], y = sc[t][(q&1)*2+1];
                uint32_t ph = packbf2(x, y);
                pa[q] = ph;
                pb[q] = packbf2(x - bf2lo(ph), y - bf2hi(ph));
            }
            // reorder: A frag = {a0=(r,klo), a1=(r+8,klo), a2=(r,khi), a3=(r+8,khi)}
            uint32_t ah4[4] = {pa[0], pa[1], pa[2], pa[3]};
            uint32_t al4[4] = {pb[0], pb[1], pb[2], pb[3]};
            #pragma unroll
            for (int p=0;p<4;p++){
                uint32_t vh4[4], vl4[4];
                uint32_t off = (uint32_t)(((p*16 + bt*8 + brow)*VLD + kt*16 + bk*8) * 2);
                ldsm_x4(vh4, uVh + off);
                ldsm_x4(vl4, uVl + off);
                mma_bf16(o[2*p],   ah4, &vh4[0]);
                mma_bf16(o[2*p],   ah4, &vl4[0]);
                mma_bf16(o[2*p],   al4, &vh4[0]);
                mma_bf16(o[2*p+1], ah4, &vh4[2]);
                mma_bf16(o[2*p+1], ah4, &vl4[2]);
                mma_bf16(o[2*p+1], al4, &vh4[2]);
            }
        }
    }

    // epilogue
    int r0 = q0 + wrow + (lane>>2), r1 = r0 + 8;
    float inv0 = 1.0f/l0, inv1 = 1.0f/l1;
    #pragma unroll
    for (int ni=0;ni<8;ni++){
        int d = ni*8 + (lane&3)*2;
        float2 w0 = make_float2(o[ni][0]*inv0, o[ni][1]*inv0);
        float2 w1 = make_float2(o[ni][2]*inv1, o[ni][3]*inv1);
        *(float2*)(out + ((size_t)b*S_ + r0)*H_ + h*HD_ + d) = w0;
        *(float2*)(out + ((size_t)b*S_ + r1)*H_ + h*HD_ + d) = w1;
    }
    if ((lane & 3) == 0){
        double es = (double)(m0 + logf(l0) - t0/l0 - 2.048e-5f)
                  + (double)(m1 + logf(l1) - t1/l1 - 2.048e-5f);
        double cs = (double)inv0 + (double)inv1;
        atomicAdd(&g_red[0][tid & 31], es);
        atomicAdd(&g_red[2][tid & 31], cs);
    }
}

__global__ void fin_kernel(float* __restrict__ out, int out_size)
{
    int t = threadIdx.x;  // 32
    double e = g_red[0][t], f = g_red[1][t], c = g_red[2][t];
    #pragma unroll
    for (int off=16; off>0; off>>=1){
        e += __shfl_xor_sync(0xffffffffu, e, off);
        f += __shfl_xor_sync(0xffffffffu, f, off);
        c += __shfl_xor_sync(0xffffffffu, c, off);
    }
    if (t == 0 && out_size >= BSH + 3){
        out[BSH+0] = (float)(e / 65536.0);
        out[BSH+1] = (float)(f / 65536.0);
        out[BSH+2] = (float)(c / 65536.0);
    }
}

extern "C" void kernel_launch(void* const* d_in, const int* in_sizes, int n_in,
                              void* d_out, int out_size) {
    const float* hs   = (const float*)d_in[0];
    const float* gov  = (const float*)d_in[1];
    const float* Wq   = (const float*)d_in[2];
    const float* bq   = (const float*)d_in[3];
    const float* Wk   = (const float*)d_in[4];
    const float* bk   = (const float*)d_in[5];
    const float* Wv   = (const float*)d_in[6];
    const float* bv   = (const float*)d_in[7];
    const float* Wgq  = (const float*)d_in[8];
    const float* bgq  = (const float*)d_in[9];
    const float* Wgk  = (const float*)d_in[10];
    const float* bgk  = (const float*)d_in[11];
    float* out = (float*)d_out;

    init_kernel<<<1, 96>>>();
    split_hs_kernel<<<B_*S_, 256>>>(hs);
    split_wT_kernel<<<dim3(16, 16, 3), 256>>>(Wq, Wk, Wv);
    cudaFuncSetAttribute(projmm_kernel, cudaFuncAttributeMaxDynamicSharedMemorySize, PROJ_SMEM);
    projmm_kernel<<<dim3(H_/128, B_*S_/128, 3), 256, PROJ_SMEM>>>(bq, bk, bv);
    gq_kernel<<<dim3(H_/256, B_), 256>>>(gov, Wgq, bgq);
    u_kernel<<<(B_*H_*NH_)/256, 256>>>(Wgk);
    c_kernel<<<1, 32>>>(bgk);
    gov_kernel<<<B_*S_, 128>>>(hs);
    cudaFuncSetAttribute(flashmma_kernel, cudaFuncAttributeMaxDynamicSharedMemorySize, FLASH_SMEM);
    flashmma_kernel<<<dim3(S_/128, NH_, B_), 256, FLASH_SMEM>>>(out);
    fin_kernel<<<1, 32>>>(out, out_size);
}

// round 15
// speedup vs baseline: 2.5066x; 1.1343x over previous
#include <cuda_runtime.h>
#include <cuda_bf16.h>
#include <math.h>
#include <stdint.h>

#define B_   2
#define S_   2048
#define H_   1024
#define NH_  16
#define HD_  64
#define BSH  (B_*S_*H_)

typedef unsigned long long u64;

// ---------------- mma.sync helpers (sm_80+ portable tensor path) -------------
__device__ __forceinline__ uint32_t smem_to_u32(const void* p){
    uint32_t a;
    asm("{ .reg .u64 t; cvta.to.shared.u64 t, %1; cvt.u32.u64 %0, t; }" : "=r"(a) : "l"(p));
    return a;
}
__device__ __forceinline__ void ldsm_x4(uint32_t* r, uint32_t addr){
    asm volatile("ldmatrix.sync.aligned.m8n8.x4.shared.b16 {%0,%1,%2,%3}, [%4];"
        : "=r"(r[0]),"=r"(r[1]),"=r"(r[2]),"=r"(r[3]) : "r"(addr));
}
__device__ __forceinline__ void ldsm_x2(uint32_t* r, uint32_t addr){
    asm volatile("ldmatrix.sync.aligned.m8n8.x2.shared.b16 {%0,%1}, [%2];"
        : "=r"(r[0]),"=r"(r[1]) : "r"(addr));
}
__device__ __forceinline__ void mma_bf16(float* d, const uint32_t* a, const uint32_t* b){
    asm volatile("mma.sync.aligned.m16n8k16.row.col.f32.bf16.bf16.f32 "
        "{%0,%1,%2,%3}, {%4,%5,%6,%7}, {%8,%9}, {%0,%1,%2,%3};"
        : "+f"(d[0]),"+f"(d[1]),"+f"(d[2]),"+f"(d[3])
        : "r"(a[0]),"r"(a[1]),"r"(a[2]),"r"(a[3]), "r"(b[0]),"r"(b[1]));
}
__device__ __forceinline__ uint32_t packbf2(float lo, float hi){
    uint32_t r; asm("cvt.rn.bf16x2.f32 %0, %1, %2;" : "=r"(r) : "f"(hi), "f"(lo)); return r;
}
__device__ __forceinline__ float bf2lo(uint32_t p){ return __uint_as_float(p << 16); }
__device__ __forceinline__ float bf2hi(uint32_t p){ return __uint_as_float(p & 0xffff0000u); }
__device__ __forceinline__ void cp16(uint32_t dst, const void* src){
    asm volatile("cp.async.cg.shared.global [%0], [%1], 16;" :: "r"(dst), "l"(src));
}
#define CP_COMMIT() asm volatile("cp.async.commit_group;" ::: "memory")
#define CP_WAIT0()  asm volatile("cp.async.wait_group 0;" ::: "memory")

// ---------------- device scratch --------------------------------------------
__device__ __nv_bfloat16 g_Qhi[B_*NH_*S_*HD_];   // [b][h][s][d] scaled
__device__ __nv_bfloat16 g_Qlo[B_*NH_*S_*HD_];
__device__ __nv_bfloat16 g_Khi[B_*NH_*S_*HD_];
__device__ __nv_bfloat16 g_Klo[B_*NH_*S_*HD_];
__device__ __nv_bfloat16 g_VThi[B_*NH_*HD_*S_];  // [b][h][d][s]
__device__ __nv_bfloat16 g_VTlo[B_*NH_*HD_*S_];
__device__ float g_gq[B_*H_];
__device__ float g_u [B_*H_*NH_];
__device__ float g_c [B_*NH_];
__device__ double g_red[3][32];
__device__ __nv_bfloat16 g_Ahi[B_*S_*H_];
__device__ __nv_bfloat16 g_Alo[B_*S_*H_];
__device__ __nv_bfloat16 g_WThi[3*H_*H_];
__device__ __nv_bfloat16 g_WTlo[3*H_*H_];

__global__ void init_kernel() {
    int t = threadIdx.x;   // 256
    if (t < 96) ((double*)g_red)[t] = 0.0;
    for (int i=t; i<B_*H_; i+=256) g_gq[i] = 0.f;
}

// ---------------- split hs into bf16 hi/lo ----------------------------------
__global__ void split_hs_kernel(const float* __restrict__ hs)
{
    int row = blockIdx.x;
    int c = threadIdx.x * 4;
    float4 v = *(const float4*)(hs + (size_t)row*H_ + c);
    uint32_t p0 = packbf2(v.x, v.y), p1 = packbf2(v.z, v.w);
    uint32_t l0 = packbf2(v.x - bf2lo(p0), v.y - bf2hi(p0));
    uint32_t l1 = packbf2(v.z - bf2lo(p1), v.w - bf2hi(p1));
    *(uint2*)(g_Ahi + (size_t)row*H_ + c) = make_uint2(p0, p1);
    *(uint2*)(g_Alo + (size_t)row*H_ + c) = make_uint2(l0, l1);
}

// ---------------- transpose + split W into bf16 WT[n][k] hi/lo --------------
__global__ void split_wT_kernel(const float* __restrict__ Wq,
                                const float* __restrict__ Wk,
                                const float* __restrict__ Wv)
{
    __shared__ float t[64][65];
    int mode = blockIdx.z;
    const float* W = mode==0 ? Wq : (mode==1 ? Wk : Wv);
    int k0 = blockIdx.x*64, n0 = blockIdx.y*64;
    int tid = threadIdx.x;
    #pragma unroll
    for (int i=0;i<4;i++){
        int idx = tid + i*256;
        int r = idx >> 4, c4 = (idx & 15) * 4;
        float4 v = *(const float4*)(W + (size_t)(k0+r)*H_ + n0 + c4);
        t[r][c4+0]=v.x; t[r][c4+1]=v.y; t[r][c4+2]=v.z; t[r][c4+3]=v.w;
    }
    __syncthreads();
    __nv_bfloat16* oh = g_WThi + (size_t)mode*H_*H_;
    __nv_bfloat16* ol = g_WTlo + (size_t)mode*H_*H_;
    #pragma unroll
    for (int i=0;i<4;i++){
        int idx = tid + i*256;
        int r = idx >> 4, c4 = (idx & 15) * 4;
        float x0=t[c4+0][r], x1=t[c4+1][r], x2=t[c4+2][r], x3=t[c4+3][r];
        uint32_t p0 = packbf2(x0, x1), p1 = packbf2(x2, x3);
        uint32_t l0 = packbf2(x0 - bf2lo(p0), x1 - bf2hi(p0));
        uint32_t l1 = packbf2(x2 - bf2lo(p1), x3 - bf2hi(p1));
        *(uint2*)(oh + (size_t)(n0+r)*H_ + k0 + c4) = make_uint2(p0, p1);
        *(uint2*)(ol + (size_t)(n0+r)*H_ + k0 + c4) = make_uint2(l0, l1);
    }
}

// ---------------- mma.sync split-bf16 projection GEMM (cp.async pipelined) ---
#define PLD 72
#define PBUF (4*128*PLD)                 // bf16 units per buffer
#define PROJ_SMEM (2*PBUF*2)             // 147456 B

__global__ void __launch_bounds__(256,1) projmm_kernel(
    const float* __restrict__ bq, const float* __restrict__ bk,
    const float* __restrict__ bv)
{
    extern __shared__ __nv_bfloat16 sm2[];
    uint32_t ub[2] = { smem_to_u32(sm2), smem_to_u32(sm2 + PBUF) };

    int tid = threadIdx.x, wid = tid >> 5, lane = tid & 31;
    int warpM = wid & 3, warpN = wid >> 2;
    int mode = blockIdx.z, m0 = blockIdx.y*128, n0 = blockIdx.x*128;
    const __nv_bfloat16* srcs[4] = {
        g_Ahi + (size_t)m0*H_, g_Alo + (size_t)m0*H_,
        g_WThi + (size_t)mode*H_*H_ + (size_t)n0*H_,
        g_WTlo + (size_t)mode*H_*H_ + (size_t)n0*H_ };
    const float* bias = mode==0 ? bq : (mode==1 ? bk : bv);

    float acc[2][8][4];
    #pragma unroll
    for (int mi=0;mi<2;mi++)
        #pragma unroll
        for (int ni=0;ni<8;ni++)
            #pragma unroll
            for (int r=0;r<4;r++) acc[mi][ni][r] = 0.f;

    int arow = lane & 15;
    int akof = (lane & 16) ? 8 : 0;
    int brow = lane & 7;
    int bkof = (lane & 8) ? 8 : 0;

    // issue chunk 0
    #pragma unroll
    for (int i=0;i<16;i++){
        int plane = i >> 2;
        int rem = tid + (i&3)*256;
        int row = rem >> 3, c8 = (rem & 7) * 8;
        cp16(ub[0] + (uint32_t)((plane*128*PLD + row*PLD + c8)*2),
             srcs[plane] + (size_t)row*H_ + c8);
    }
    CP_COMMIT();

    for (int kc = 0; kc < 16; kc++){
        CP_WAIT0();
        __syncthreads();
        if (kc < 15){
            #pragma unroll
            for (int i=0;i<16;i++){
                int plane = i >> 2;
                int rem = tid + (i&3)*256;
                int row = rem >> 3, c8 = (rem & 7) * 8;
                cp16(ub[(kc+1)&1] + (uint32_t)((plane*128*PLD + row*PLD + c8)*2),
                     srcs[plane] + (size_t)row*H_ + (kc+1)*64 + c8);
            }
            CP_COMMIT();
        }
        uint32_t uAh = ub[kc&1];
        uint32_t uAl = uAh + 128*PLD*2;
        uint32_t uBh = uAh + 2*128*PLD*2;
        uint32_t uBl = uAh + 3*128*PLD*2;

        #pragma unroll
        for (int ks=0; ks<4; ks++){
            uint32_t ah[2][4], al[2][4], bh[8][2], bl[8][2];
            #pragma unroll
            for (int mi=0;mi<2;mi++){
                uint32_t off = (uint32_t)(((warpM*32 + mi*16 + arow)*PLD + ks*16 + akof) * 2);
                ldsm_x4(ah[mi], uAh + off);
                ldsm_x4(al[mi], uAl + off);
            }
            #pragma unroll
            for (int ni=0;ni<8;ni++){
                uint32_t off = (uint32_t)(((warpN*64 + ni*8 + brow)*PLD + ks*16 + bkof) * 2);
                ldsm_x2(bh[ni], uBh + off);
                ldsm_x2(bl[ni], uBl + off);
            }
            #pragma unroll
            for (int mi=0;mi<2;mi++)
                #pragma unroll
                for (int ni=0;ni<8;ni++){
                    mma_bf16(acc[mi][ni], ah[mi], bh[ni]);
                    mma_bf16(acc[mi][ni], ah[mi], bl[ni]);
                    mma_bf16(acc[mi][ni], al[mi], bh[ni]);
                }
        }
    }

    float bval[8][2];
    #pragma unroll
    for (int ni=0;ni<8;ni++)
        #pragma unroll
        for (int c=0;c<2;c++)
            bval[ni][c] = __ldg(bias + n0 + warpN*64 + ni*8 + (lane&3)*2 + c);

    int hh = (n0 >> 6) + warpN;
    if (mode < 2){
        float scale = (mode==0) ? 0.125f : 1.0f;
        __nv_bfloat16* dh = (mode==0) ? g_Qhi : g_Khi;
        __nv_bfloat16* dl = (mode==0) ? g_Qlo : g_Klo;
        #pragma unroll
        for (int mi=0;mi<2;mi++)
            #pragma unroll
            for (int rg=0;rg<2;rg++){
                int m = m0 + warpM*32 + mi*16 + (lane>>2) + rg*8;
                int bidx = m >> 11, s = m & 2047;
                size_t base = ((size_t)(bidx*NH_+hh)*S_ + s)*HD_;
                #pragma unroll
                for (int ni=0;ni<8;ni++){
                    float v0 = (acc[mi][ni][rg*2+0] + bval[ni][0]) * scale;
                    float v1 = (acc[mi][ni][rg*2+1] + bval[ni][1]) * scale;
                    uint32_t ph = packbf2(v0, v1);
                    uint32_t pl = packbf2(v0 - bf2lo(ph), v1 - bf2hi(ph));
                    int doff = ni*8 + (lane&3)*2;
                    *(uint32_t*)(dh + base + doff) = ph;
                    *(uint32_t*)(dl + base + doff) = pl;
                }
            }
    } else {
        #pragma unroll
        for (int mi=0;mi<2;mi++)
            #pragma unroll
            for (int rg=0;rg<2;rg++){
                int m = m0 + warpM*32 + mi*16 + (lane>>2) + rg*8;
                int bidx = m >> 11, s = m & 2047;
                size_t base = (size_t)(bidx*NH_+hh)*HD_*S_;
                #pragma unroll
                for (int ni=0;ni<8;ni++)
                    #pragma unroll
                    for (int c=0;c<2;c++){
                        int d = ni*8 + (lane&3)*2 + c;
                        float v = acc[mi][ni][rg*2+c] + bval[ni][c];
                        __nv_bfloat16 vh = __float2bfloat16_rn(v);
                        size_t vi = base + (size_t)d*S_ + s;
                        g_VThi[vi] = vh;
                        g_VTlo[vi] = __float2bfloat16_rn(v - __bfloat162float(vh));
                    }
            }
    }
}

// ---------------- governance small kernels ----------------------------------
__global__ void gq_kernel(const float* __restrict__ gov,
                          const float* __restrict__ Wgq,
                          const float* __restrict__ bgq)
{
    __shared__ float sg[128];
    int b = blockIdx.y, kz = blockIdx.z;       // 8 k-chunks of 128
    int n = blockIdx.x*256 + threadIdx.x;
    if (threadIdx.x < 128)
        sg[threadIdx.x] = gov[b*H_ + kz*128 + threadIdx.x];
    __syncthreads();
    float acc = (kz == 0) ? bgq[n] : 0.f;
    #pragma unroll 8
    for (int k=0;k<128;k++)
        acc += sg[k] * Wgq[(size_t)(kz*128+k)*H_ + n];
    atomicAdd(&g_gq[b*H_ + n], acc);
}

__global__ void u_kernel(const float* __restrict__ Wgk)
{
    int idx = blockIdx.x*256 + threadIdx.x;
    int h = idx & 15;
    int k = (idx >> 4) & 1023;
    int b = idx >> 14;
    const float* wrow = Wgk + (size_t)k*H_ + h*HD_;
    const float* gq   = g_gq + b*H_ + h*HD_;
    float acc = 0.f;
    #pragma unroll
    for (int d=0; d<HD_; d+=4){
        float4 w = *(const float4*)(wrow + d);
        float4 g = *(const float4*)(gq + d);
        acc += w.x*g.x + w.y*g.y + w.z*g.z + w.w*g.w;
    }
    g_u[idx] = acc;
}

__global__ void c_kernel(const float* __restrict__ bgk)
{
    int t = threadIdx.x;
    if (t < 32){
        int b = t >> 4, h = t & 15;
        const float* gq = g_gq + b*H_ + h*HD_;
        const float* bp = bgk + h*HD_;
        float acc = 0.f;
        #pragma unroll
        for (int d=0;d<HD_;d++) acc += bp[d]*gq[d];
        g_c[t] = acc;
    }
}

__global__ void gov_kernel(const float* __restrict__ hs)
{
    __shared__ float shs[H_];
    __shared__ float sred[4][16];
    int bs_ = blockIdx.x;
    int b = bs_ >> 11;
    int tid = threadIdx.x;   // 128
    const float* row = hs + (size_t)bs_ * H_;
    for (int i=tid; i<H_/4; i+=128)
        *(float4*)&shs[i*4] = *(const float4*)(row + i*4);
    __syncthreads();
    float acc[16];
    #pragma unroll
    for (int h=0;h<16;h++) acc[h]=0.f;
    const float* ub = g_u + b*16384;
    #pragma unroll
    for (int kk=0;kk<8;kk++){
        int k = kk*128 + tid;
        float hv = shs[k];
        const float* up = ub + k*16;
        #pragma unroll
        for (int h4=0; h4<4; h4++){
            float4 u4 = *(const float4*)(up + h4*4);
            acc[h4*4+0] += hv*u4.x;
            acc[h4*4+1] += hv*u4.y;
            acc[h4*4+2] += hv*u4.z;
            acc[h4*4+3] += hv*u4.w;
        }
    }
    #pragma unroll
    for (int h=0;h<16;h++){
        #pragma unroll
        for (int off=16; off>0; off>>=1)
            acc[h] += __shfl_xor_sync(0xffffffffu, acc[h], off);
    }
    int warp = tid>>5, lane = tid&31;
    if (lane==0){
        #pragma unroll
        for (int h=0;h<16;h++) sred[warp][h] = acc[h];
    }
    __syncthreads();
    if (tid < 16){
        float g = sred[0][tid]+sred[1][tid]+sred[2][tid]+sred[3][tid] + g_c[b*16+tid];
        float v = fabsf(g);
        #pragma unroll
        for (int off=8; off>0; off>>=1)
            v += __shfl_xor_sync(0xffffu, v, off);
        if (tid==0) atomicAdd(&g_red[1][bs_ & 31], (double)v);
    }
}

// ---------------- flash attention mma.sync (cp.async pipelined) --------------
#define KLD 72
#define VLD 136
#define FBUF (2*128*KLD + 2*64*VLD)      // bf16 units per buffer = 35840
#define FLASH_SMEM (2*FBUF*2)            // 143360 B

__global__ void __launch_bounds__(256,1) flashmma_kernel(float* __restrict__ out)
{
    extern __shared__ __nv_bfloat16 fsm[];
    uint32_t fb[2] = { smem_to_u32(fsm), smem_to_u32(fsm + FBUF) };

    int q0 = blockIdx.x * 128;
    int h  = blockIdx.y;
    int b  = blockIdx.z;
    size_t bh = (size_t)(b*NH_ + h);
    const __nv_bfloat16* Qh_ = g_Qhi + bh*S_*HD_;
    const __nv_bfloat16* Ql_ = g_Qlo + bh*S_*HD_;
    const __nv_bfloat16* ksrc[2] = { g_Khi + bh*S_*HD_, g_Klo + bh*S_*HD_ };
    const __nv_bfloat16* vsrc[2] = { g_VThi + bh*HD_*S_, g_VTlo + bh*HD_*S_ };

    int tid = threadIdx.x, wid = tid >> 5, lane = tid & 31;
    int wrow = wid * 16;
    int arow = lane & 15;
    int akof = (lane & 16) ? 8 : 0;
    int brow = lane & 7;
    int bt = (lane >> 4) & 1;
    int bk = (lane >> 3) & 1;

    // stage Q into buf0 K-planes, read fragments
    {
        __nv_bfloat16* s0 = fsm;
        #pragma unroll
        for (int i=0;i<4;i++){
            int idx = tid + i*256;
            int row = idx >> 3, c8 = (idx & 7) * 8;
            *(uint4*)(s0 + row*KLD + c8)          = *(const uint4*)(Qh_ + (size_t)(q0+row)*HD_ + c8);
            *(uint4*)(s0 + 128*KLD + row*KLD + c8) = *(const uint4*)(Ql_ + (size_t)(q0+row)*HD_ + c8);
        }
    }
    __syncthreads();
    uint32_t qh[4][4], ql[4][4];
    #pragma unroll
    for (int kt=0; kt<4; kt++){
        uint32_t off = (uint32_t)(((wrow + arow)*KLD + kt*16 + akof) * 2);
        ldsm_x4(qh[kt], fb[0] + off);
        ldsm_x4(ql[kt], fb[0] + 128*KLD*2 + off);
    }
    __syncthreads();

    // issue tile 0
    #pragma unroll
    for (int i=0;i<16;i++){
        int rem = tid + (i&3)*256;
        if (i < 8){
            int pl = i >> 2;
            int row = rem >> 3, c8 = (rem & 7) * 8;
            cp16(fb[0] + (uint32_t)((pl*128*KLD + row*KLD + c8)*2),
                 ksrc[pl] + (size_t)row*HD_ + c8);
        } else {
            int pl = (i >> 2) & 1;
            int row = rem >> 4, c8 = (rem & 15) * 8;
            cp16(fb[0] + (uint32_t)((2*128*KLD + pl*64*VLD + row*VLD + c8)*2),
                 vsrc[pl] + (size_t)row*S_ + c8);
        }
    }
    CP_COMMIT();

    float o[8][4];
    #pragma unroll
    for (int ni=0;ni<8;ni++)
        #pragma unroll
        for (int r=0;r<4;r++) o[ni][r] = 0.f;
    float m0=-1e30f, m1=-1e30f, l0=0.f, l1=0.f, t0=0.f, t1=0.f;

    for (int jt = 0; jt < 16; jt++){
        CP_WAIT0();
        __syncthreads();
        if (jt < 15){
            int j1 = (jt+1)*128;
            #pragma unroll
            for (int i=0;i<16;i++){
                int rem = tid + (i&3)*256;
                if (i < 8){
                    int pl = i >> 2;
                    int row = rem >> 3, c8 = (rem & 7) * 8;
                    cp16(fb[(jt+1)&1] + (uint32_t)((pl*128*KLD + row*KLD + c8)*2),
                         ksrc[pl] + (size_t)(j1+row)*HD_ + c8);
                } else {
                    int pl = (i >> 2) & 1;
                    int row = rem >> 4, c8 = (rem & 15) * 8;
                    cp16(fb[(jt+1)&1] + (uint32_t)((2*128*KLD + pl*64*VLD + row*VLD + c8)*2),
                         vsrc[pl] + (size_t)row*S_ + j1 + c8);
                }
            }
            CP_COMMIT();
        }
        uint32_t uKh = fb[jt&1];
        uint32_t uKl = uKh + 128*KLD*2;
        uint32_t uVh = uKh + 2*128*KLD*2;
        uint32_t uVl = uVh + 64*VLD*2;

        // S = Q K^T
        float sc[16][4];
        #pragma unroll
        for (int t=0;t<16;t++)
            #pragma unroll
            for (int r=0;r<4;r++) sc[t][r] = 0.f;
        #pragma unroll
        for (int ks=0; ks<4; ks++){
            #pragma unroll
            for (int p=0;p<8;p++){
                uint32_t kh4[4], kl4[4];
                uint32_t off = (uint32_t)(((p*16 + bt*8 + brow)*KLD + ks*16 + bk*8) * 2);
                ldsm_x4(kh4, uKh + off);
                ldsm_x4(kl4, uKl + off);
                mma_bf16(sc[2*p],   qh[ks], &kh4[0]);
                mma_bf16(sc[2*p],   qh[ks], &kl4[0]);
                mma_bf16(sc[2*p],   ql[ks], &kh4[0]);
                mma_bf16(sc[2*p+1], qh[ks], &kh4[2]);
                mma_bf16(sc[2*p+1], qh[ks], &kl4[2]);
                mma_bf16(sc[2*p+1], ql[ks], &kh4[2]);
            }
        }

        // online softmax
        float mx0 = -1e30f, mx1 = -1e30f;
        #pragma unroll
        for (int t=0;t<16;t++){
            mx0 = fmaxf(mx0, fmaxf(sc[t][0], sc[t][1]));
            mx1 = fmaxf(mx1, fmaxf(sc[t][2], sc[t][3]));
        }
        #pragma unroll
        for (int off=1; off<4; off<<=1){
            mx0 = fmaxf(mx0, __shfl_xor_sync(0xffffffffu, mx0, off));
            mx1 = fmaxf(mx1, __shfl_xor_sync(0xffffffffu, mx1, off));
        }
        float mn0 = fmaxf(m0, mx0), mn1 = fmaxf(m1, mx1);
        float la0=0.f, ta0=0.f, la1=0.f, ta1=0.f;
        #pragma unroll
        for (int t=0;t<16;t++){
            float s0 = sc[t][0], s1 = sc[t][1], s2 = sc[t][2], s3 = sc[t][3];
            float e0 = __expf(s0-mn0), e1 = __expf(s1-mn0);
            float e2 = __expf(s2-mn1), e3 = __expf(s3-mn1);
            la0 += e0+e1; ta0 += e0*s0 + e1*s1;
            la1 += e2+e3; ta1 += e2*s2 + e3*s3;
            sc[t][0]=e0; sc[t][1]=e1; sc[t][2]=e2; sc[t][3]=e3;
        }
        #pragma unroll
        for (int off=1; off<4; off<<=1){
            la0 += __shfl_xor_sync(0xffffffffu, la0, off);
            ta0 += __shfl_xor_sync(0xffffffffu, ta0, off);
            la1 += __shfl_xor_sync(0xffffffffu, la1, off);
            ta1 += __shfl_xor_sync(0xffffffffu, ta1, off);
        }
        float scl0 = __expf(m0-mn0), scl1 = __expf(m1-mn1);
        l0 = l0*scl0 + la0; t0 = t0*scl0 + ta0; m0 = mn0;
        l1 = l1*scl1 + la1; t1 = t1*scl1 + ta1; m1 = mn1;
        #pragma unroll
        for (int ni=0;ni<8;ni++){
            o[ni][0]*=scl0; o[ni][1]*=scl0; o[ni][2]*=scl1; o[ni][3]*=scl1;
        }

        // O += P V
        #pragma unroll
        for (int kt=0; kt<8; kt++){
            uint32_t pa[4], pb[4];
            #pragma unroll
            for (int q=0;q<4;q++){
                int t = 2*kt + (q>>1);
                float x = sc[t][(q&1)*2+0], y = sc[t][(q&1)*2+1];
                uint32_t ph = packbf2(x, y);
                pa[q] = ph;
                pb[q] = packbf2(x - bf2lo(ph), y - bf2hi(ph));
            }
            uint32_t ah4[4] = {pa[0], pa[1], pa[2], pa[3]};
            uint32_t al4[4] = {pb[0], pb[1], pb[2], pb[3]};
            #pragma unroll
            for (int p=0;p<4;p++){
                uint32_t vh4[4], vl4[4];
                uint32_t off = (uint32_t)(((p*16 + bt*8 + brow)*VLD + kt*16 + bk*8) * 2);
                ldsm_x4(vh4, uVh + off);
                ldsm_x4(vl4, uVl + off);
                mma_bf16(o[2*p],   ah4, &vh4[0]);
                mma_bf16(o[2*p],   ah4, &vl4[0]);
                mma_bf16(o[2*p],   al4, &vh4[0]);
                mma_bf16(o[2*p+1], ah4, &vh4[2]);
                mma_bf16(o[2*p+1], ah4, &vl4[2]);
                mma_bf16(o[2*p+1], al4, &vh4[2]);
            }
        }
    }

    // epilogue
    int r0 = q0 + wrow + (lane>>2), r1 = r0 + 8;
    float inv0 = 1.0f/l0, inv1 = 1.0f/l1;
    #pragma unroll
    for (int ni=0;ni<8;ni++){
        int d = ni*8 + (lane&3)*2;
        float2 w0 = make_float2(o[ni][0]*inv0, o[ni][1]*inv0);
        float2 w1 = make_float2(o[ni][2]*inv1, o[ni][3]*inv1);
        *(float2*)(out + ((size_t)b*S_ + r0)*H_ + h*HD_ + d) = w0;
        *(float2*)(out + ((size_t)b*S_ + r1)*H_ + h*HD_ + d) = w1;
    }
    if ((lane & 3) == 0){
        double es = (double)(m0 + logf(l0) - t0/l0 - 2.048e-5f)
                  + (double)(m1 + logf(l1) - t1/l1 - 2.048e-5f);
        double cs = (double)inv0 + (double)inv1;
        atomicAdd(&g_red[0][tid & 31], es);
        atomicAdd(&g_red[2][tid & 31], cs);
    }
}

__global__ void fin_kernel(float* __restrict__ out, int out_size)
{
    int t = threadIdx.x;  // 32
    double e = g_red[0][t], f = g_red[1][t], c = g_red[2][t];
    #pragma unroll
    for (int off=16; off>0; off>>=1){
        e += __shfl_xor_sync(0xffffffffu, e, off);
        f += __shfl_xor_sync(0xffffffffu, f, off);
        c += __shfl_xor_sync(0xffffffffu, c, off);
    }
    if (t == 0 && out_size >= BSH + 3){
        out[BSH+0] = (float)(e / 65536.0);
        out[BSH+1] = (float)(f / 65536.0);
        out[BSH+2] = (float)(c / 65536.0);
    }
}

extern "C" void kernel_launch(void* const* d_in, const int* in_sizes, int n_in,
                              void* d_out, int out_size) {
    const float* hs   = (const float*)d_in[0];
    const float* gov  = (const float*)d_in[1];
    const float* Wq   = (const float*)d_in[2];
    const float* bq   = (const float*)d_in[3];
    const float* Wk   = (const float*)d_in[4];
    const float* bk   = (const float*)d_in[5];
    const float* Wv   = (const float*)d_in[6];
    const float* bv   = (const float*)d_in[7];
    const float* Wgq  = (const float*)d_in[8];
    const float* bgq  = (const float*)d_in[9];
    const float* Wgk  = (const float*)d_in[10];
    const float* bgk  = (const float*)d_in[11];
    float* out = (float*)d_out;

    init_kernel<<<1, 256>>>();
    split_hs_kernel<<<B_*S_, 256>>>(hs);
    split_wT_kernel<<<dim3(16, 16, 3), 256>>>(Wq, Wk, Wv);
    cudaFuncSetAttribute(projmm_kernel, cudaFuncAttributeMaxDynamicSharedMemorySize, PROJ_SMEM);
    projmm_kernel<<<dim3(H_/128, B_*S_/128, 3), 256, PROJ_SMEM>>>(bq, bk, bv);
    gq_kernel<<<dim3(H_/256, B_, 8), 256>>>(gov, Wgq, bgq);
    u_kernel<<<(B_*H_*NH_)/256, 256>>>(Wgk);
    c_kernel<<<1, 32>>>(bgk);
    gov_kernel<<<B_*S_, 128>>>(hs);
    cudaFuncSetAttribute(flashmma_kernel, cudaFuncAttributeMaxDynamicSharedMemorySize, FLASH_SMEM);
    flashmma_kernel<<<dim3(S_/128, NH_, B_), 256, FLASH_SMEM>>>(out);
    fin_kernel<<<1, 32>>>(out, out_size);
}